// round 14
// baseline (speedup 1.0000x reference)
#include <cuda_runtime.h>
#include <cuda_bf16.h>
#include <cstdint>

// ---------------- model dims ----------------
#define B_    8
#define L_    512
#define D_IN  128
#define D_MODEL 512
#define N_LAYERS 2
#define D_STATE 16
#define D_CONV  4
#define D_INNER 1024
#define DT_RANK 32
#define ML (B_ * L_)
#define XKS 8                      // split-K / d-slice factor for fused conv+x_proj
#define NCH 8                      // scan chunks over L
#define CHL (L_ / NCH)             // 64 steps per chunk

// ---------------- scratch ----------------
__device__ float g_xz[ML * 2 * D_INNER];
__device__ float g_xc[ML * D_INNER];
__device__ float g_xdbl[ML * 64];
__device__ float g_xpart[XKS * ML * 64];
__device__ float g_dt[ML * D_INNER];
__device__ float g_ympart[NCH * B_ * D_INNER];

// bf16 hi/lo planes
__device__ __align__(16) __nv_bfloat16 g_xh[ML * D_IN];
__device__ __align__(16) __nv_bfloat16 g_xl[ML * D_IN];
__device__ __align__(16) __nv_bfloat16 g_piwh[D_MODEL * D_IN];
__device__ __align__(16) __nv_bfloat16 g_piwl[D_MODEL * D_IN];
__device__ __align__(16) __nv_bfloat16 g_inwh[N_LAYERS * 2 * D_INNER * D_MODEL];
__device__ __align__(16) __nv_bfloat16 g_inwl[N_LAYERS * 2 * D_INNER * D_MODEL];
__device__ __align__(16) __nv_bfloat16 g_outwh[N_LAYERS * D_MODEL * D_INNER];
__device__ __align__(16) __nv_bfloat16 g_outwl[N_LAYERS * D_MODEL * D_INNER];
__device__ __align__(16) __nv_bfloat16 g_xpwh[N_LAYERS * 64 * D_INNER];
__device__ __align__(16) __nv_bfloat16 g_xpwl[N_LAYERS * 64 * D_INNER];
__device__ __align__(16) __nv_bfloat16 g_dtwh[N_LAYERS * D_INNER * 64];
__device__ __align__(16) __nv_bfloat16 g_dtwl[N_LAYERS * D_INNER * 64];
// activation planes
__device__ __align__(16) __nv_bfloat16 g_hh[ML * D_MODEL];
__device__ __align__(16) __nv_bfloat16 g_hl[ML * D_MODEL];
__device__ __align__(16) __nv_bfloat16 g_xdblh[ML * 64];
__device__ __align__(16) __nv_bfloat16 g_xdbll[ML * 64];
__device__ __align__(16) __nv_bfloat16 g_yh[ML * D_INNER];
__device__ __align__(16) __nv_bfloat16 g_yl[ML * D_INNER];

__device__ __forceinline__ float act_silu(float v) { return v / (1.f + __expf(-v)); }
__device__ __forceinline__ float act_softplus(float v) { return (v > 20.f) ? v : log1pf(__expf(v)); }

// =====================================================================
// PTX helpers
// =====================================================================
__device__ __forceinline__ void ldsm_x4(uint32_t* r, uint32_t addr) {
    asm volatile("ldmatrix.sync.aligned.m8n8.x4.shared.b16 {%0,%1,%2,%3}, [%4];"
                 : "=r"(r[0]), "=r"(r[1]), "=r"(r[2]), "=r"(r[3]) : "r"(addr));
}
__device__ __forceinline__ void mma16816(float* c, const uint32_t* a, const uint32_t* b) {
    asm volatile(
        "mma.sync.aligned.m16n8k16.row.col.f32.bf16.bf16.f32 "
        "{%0,%1,%2,%3}, {%4,%5,%6,%7}, {%8,%9}, {%0,%1,%2,%3};"
        : "+f"(c[0]), "+f"(c[1]), "+f"(c[2]), "+f"(c[3])
        : "r"(a[0]), "r"(a[1]), "r"(a[2]), "r"(a[3]), "r"(b[0]), "r"(b[1]));
}
__device__ __forceinline__ void cp16(uint32_t dst, const void* src) {
    asm volatile("cp.async.cg.shared.global [%0], [%1], 16;" :: "r"(dst), "l"(src));
}
#define CP_COMMIT() asm volatile("cp.async.commit_group;" ::: "memory")
#define CP_WAIT(n)  asm volatile("cp.async.wait_group %0;" :: "n"(n) : "memory")

__device__ __forceinline__ uint32_t bf2_bits(__nv_bfloat162 v) {
    return *reinterpret_cast<const uint32_t*>(&v);
}
__device__ __forceinline__ void split4(float4 v, uint2& h, uint2& l) {
    __nv_bfloat162 h0 = __floats2bfloat162_rn(v.x, v.y);
    __nv_bfloat162 h1 = __floats2bfloat162_rn(v.z, v.w);
    __nv_bfloat162 l0 = __floats2bfloat162_rn(v.x - __bfloat162float(h0.x),
                                              v.y - __bfloat162float(h0.y));
    __nv_bfloat162 l1 = __floats2bfloat162_rn(v.z - __bfloat162float(h1.x),
                                              v.w - __bfloat162float(h1.y));
    h = make_uint2(bf2_bits(h0), bf2_bits(h1));
    l = make_uint2(bf2_bits(l0), bf2_bits(l1));
}

// ---------------- all fp32->bf16 hi/lo splits in ONE launch ----------------
__global__ void cvt_all(const float* __restrict__ x,    __nv_bfloat16* xh,    __nv_bfloat16* xl,
                        const float* __restrict__ piw,  __nv_bfloat16* piwh,  __nv_bfloat16* piwl,
                        const float* __restrict__ inw,  __nv_bfloat16* inwh,  __nv_bfloat16* inwl,
                        const float* __restrict__ outw, __nv_bfloat16* outwh, __nv_bfloat16* outwl,
                        const float* __restrict__ xpw,  __nv_bfloat16* xpwh,  __nv_bfloat16* xpwl,
                        const float* __restrict__ dtw,  __nv_bfloat16* dtwh,  __nv_bfloat16* dtwl)
{
    int i = blockIdx.x * blockDim.x + threadIdx.x;
    const int n_x   = ML * D_IN / 4;
    const int n_piw = D_MODEL * D_IN / 4;
    const int n_in  = N_LAYERS * 2 * D_INNER * D_MODEL / 4;
    // only layer-0 out_proj needs planes (last layer handled via mean push)
    const int n_out = D_MODEL * D_INNER / 4;
    const int n_xp  = N_LAYERS * 64 * D_INNER / 4;
    const int n_dt  = N_LAYERS * D_INNER * 8;
    const float* src; __nv_bfloat16 *h, *l; int si, di;
    if (i < n_x) { src = x; h = xh; l = xl; si = i; di = i; }
    else if ((i -= n_x) < n_piw) { src = piw; h = piwh; l = piwl; si = i; di = i; }
    else if ((i -= n_piw) < n_in) { src = inw; h = inwh; l = inwl; si = i; di = i; }
    else if ((i -= n_in) < n_out) { src = outw; h = outwh; l = outwl; si = i; di = i; }
    else if ((i -= n_out) < n_xp) { src = xpw; h = xpwh; l = xpwl; si = i; di = i; }
    else if ((i -= n_xp) < n_dt) {
        int row = i >> 3, q = i & 7;
        src = dtw; h = dtwh; l = dtwl;
        si = row * 8 + q;
        di = row * 16 + q;
    }
    else return;
    uint2 hh, ll;
    split4(reinterpret_cast<const float4*>(src)[si], hh, ll);
    reinterpret_cast<uint2*>(h)[di] = hh;
    reinterpret_cast<uint2*>(l)[di] = ll;
}

// ---------------- common epilogue store ----------------
__device__ __forceinline__ void epi_store(
    float* C, __nv_bfloat16* Ch, __nv_bfloat16* Cl,
    const float* bias, int act, int ldc,
    int r0, int r1, int col, const float* a)
{
    const float b0 = bias ? __ldg(&bias[col]) : 0.f;
    const float b1 = bias ? __ldg(&bias[col + 1]) : 0.f;
    float2 v0 = make_float2(a[0] + b0, a[1] + b1);
    float2 v1 = make_float2(a[2] + b0, a[3] + b1);
    if (act == 1) {
        v0.x = act_softplus(v0.x); v0.y = act_softplus(v0.y);
        v1.x = act_softplus(v1.x); v1.y = act_softplus(v1.y);
    }
    if (C) {
        *reinterpret_cast<float2*>(&C[(size_t)r0 * ldc + col]) = v0;
        *reinterpret_cast<float2*>(&C[(size_t)r1 * ldc + col]) = v1;
    }
    if (Ch) {
        uint2 h0, l0, h1, l1;
        split4(make_float4(v0.x, v0.y, 0.f, 0.f), h0, l0);
        split4(make_float4(v1.x, v1.y, 0.f, 0.f), h1, l1);
        *reinterpret_cast<uint32_t*>(&Ch[(size_t)r0 * ldc + col]) = h0.x;
        *reinterpret_cast<uint32_t*>(&Ch[(size_t)r1 * ldc + col]) = h1.x;
        *reinterpret_cast<uint32_t*>(&Cl[(size_t)r0 * ldc + col]) = l0.x;
        *reinterpret_cast<uint32_t*>(&Cl[(size_t)r1 * ldc + col]) = l1.x;
    }
}

// =====================================================================
// gemm_mma_s v3 (r10/r11 WINNER, unchanged)
// =====================================================================
#define MMS_SMEM_BYTES 98304

__global__ __launch_bounds__(256, 2) void gemm_mma_s(
    const __nv_bfloat16* __restrict__ Ah, const __nv_bfloat16* __restrict__ Al, int lda,
    const __nv_bfloat16* __restrict__ Wh, const __nv_bfloat16* __restrict__ Wl, int ldw,
    const float* __restrict__ bias, float* __restrict__ C,
    __nv_bfloat16* __restrict__ Ch, __nv_bfloat16* __restrict__ Cl,
    int ldc, int K, int act, size_t zstride)
{
    extern __shared__ char smem[];
    const uint32_t sbase = (uint32_t)__cvta_generic_to_shared(smem);
    const int tid = threadIdx.x;
    const int lane = tid & 31;
    const int wid = tid >> 5;
    const int wm = wid & 3;
    const int wn = wid >> 2;
    const int bm = blockIdx.y * 128;
    const int bn = blockIdx.x * 64;
    {
        const int z = blockIdx.z;
        Ah += (size_t)z * K; Al += (size_t)z * K;
        Wh += (size_t)z * K; Wl += (size_t)z * K;
        C  += (size_t)z * zstride;
    }

    const int rf = tid >> 3;
    const int sf = tid & 7;
    const uint32_t swb = (uint32_t)(rf * 128 + sf * 16) ^ (((uint32_t)rf & 7u) << 4);

    auto fill = [&](int buf, int k0) {
        const uint32_t bb = sbase + (uint32_t)buf * 49152;
        #pragma unroll
        for (int u = 0; u < 4; u++) {
            const int row = rf + u * 32;
            const uint32_t sw = swb + (uint32_t)(u * 4096);
            const size_t go = (size_t)(bm + row) * lda + k0 + sf * 8;
            cp16(bb + sw, Ah + go);
            cp16(bb + 16384 + sw, Al + go);
        }
        #pragma unroll
        for (int u = 0; u < 2; u++) {
            const int row = rf + u * 32;
            const uint32_t sw = swb + (uint32_t)(u * 4096);
            const size_t go = (size_t)(bn + row) * ldw + k0 + sf * 8;
            cp16(bb + 32768 + sw, Wh + go);
            cp16(bb + 40960 + sw, Wl + go);
        }
    };

    const int l7 = lane & 7;
    const uint32_t xorv = (uint32_t)l7 << 4;
    const int a_row = wm * 32 + l7 + ((lane >> 3) & 1) * 8;
    const uint32_t a_kb = (uint32_t)((lane >> 4) & 1) * 16;
    const int b_row = wn * 32 + ((lane >> 4) & 1) * 8 + l7;
    const uint32_t b_kb = (uint32_t)((lane >> 3) & 1) * 16;

    float acc[2][4][4];
    #pragma unroll
    for (int i = 0; i < 2; i++)
        #pragma unroll
        for (int j = 0; j < 4; j++)
            #pragma unroll
            for (int r = 0; r < 4; r++) acc[i][j][r] = 0.f;

    const int nt = K / 64;

    fill(0, 0);
    CP_COMMIT();

    for (int t = 0; t < nt; t++) {
        const int buf = t & 1;
        if (t + 1 < nt) {
            fill(buf ^ 1, (t + 1) * 64);
            CP_COMMIT();
            CP_WAIT(1);
        } else {
            CP_WAIT(0);
        }
        __syncthreads();

        const uint32_t bb = sbase + (uint32_t)buf * 49152;
        #pragma unroll
        for (int kk = 0; kk < 4; kk++) {
            const uint32_t koff_a = ((uint32_t)(kk * 32) + a_kb) ^ xorv;
            const uint32_t koff_b = ((uint32_t)(kk * 32) + b_kb) ^ xorv;
            uint32_t ah[2][4], al[2][4], bh[2][4], bl[2][4];
            #pragma unroll
            for (int i = 0; i < 2; i++) {
                uint32_t ad = bb + (uint32_t)((a_row + i * 16) * 128) + koff_a;
                ldsm_x4(ah[i], ad);
                ldsm_x4(al[i], ad + 16384);
            }
            #pragma unroll
            for (int jj = 0; jj < 2; jj++) {
                uint32_t bd = bb + 32768 + (uint32_t)((b_row + jj * 16) * 128) + koff_b;
                ldsm_x4(bh[jj], bd);
                ldsm_x4(bl[jj], bd + 8192);
            }
            #pragma unroll
            for (int i = 0; i < 2; i++)
                #pragma unroll
                for (int j = 0; j < 4; j++)
                    mma16816(acc[i][j], ah[i], &bh[j >> 1][(j & 1) * 2]);
            #pragma unroll
            for (int i = 0; i < 2; i++)
                #pragma unroll
                for (int j = 0; j < 4; j++)
                    mma16816(acc[i][j], ah[i], &bl[j >> 1][(j & 1) * 2]);
            #pragma unroll
            for (int i = 0; i < 2; i++)
                #pragma unroll
                for (int j = 0; j < 4; j++)
                    mma16816(acc[i][j], al[i], &bh[j >> 1][(j & 1) * 2]);
        }
        __syncthreads();
    }

    const int g = lane >> 2;
    const int t4 = lane & 3;
    #pragma unroll
    for (int i = 0; i < 2; i++) {
        const int r0 = bm + wm * 32 + i * 16 + g;
        const int r1 = r0 + 8;
        #pragma unroll
        for (int j = 0; j < 4; j++) {
            const int col = bn + wn * 32 + j * 8 + t4 * 2;
            epi_store(C, Ch, Cl, bias, act, ldc, r0, r1, col, acc[i][j]);
        }
    }
}

// =====================================================================
// FUSED conv + x_proj GEMM (r13 WINNER, unchanged)
// =====================================================================
__global__ __launch_bounds__(256, 2) void conv_xproj_mma(
    const float* __restrict__ xz,
    const float* __restrict__ cw,
    const float* __restrict__ cb,
    float* __restrict__ xc,
    const __nv_bfloat16* __restrict__ Wh,
    const __nv_bfloat16* __restrict__ Wl,
    float* __restrict__ C)
{
    extern __shared__ char smem[];
    const uint32_t sbase = (uint32_t)__cvta_generic_to_shared(smem);
    const int tid = threadIdx.x;
    const int lane = tid & 31;
    const int wid = tid >> 5;
    const int wm = wid & 3;
    const int wn = wid >> 2;
    const int bm = blockIdx.y * 128;
    const int z = blockIdx.z;
    const int kbase = z * 128;
    C += (size_t)z * ML * 64;

    const int rf = tid >> 3;
    const int sf = tid & 7;
    const uint32_t swb = (uint32_t)(rf * 128 + sf * 16) ^ (((uint32_t)rf & 7u) << 4);

    auto fillW = [&](int buf, int t) {
        const uint32_t bb = sbase + (uint32_t)buf * 49152;
        const int k0 = kbase + t * 64;
        #pragma unroll
        for (int u = 0; u < 2; u++) {
            const int row = rf + u * 32;
            const uint32_t sw = swb + (uint32_t)(u * 4096);
            const size_t go = (size_t)row * D_INNER + k0 + sf * 8;
            cp16(bb + 32768 + sw, Wh + go);
            cp16(bb + 40960 + sw, Wl + go);
        }
    };

    const int d4g = (tid & 15) * 4;
    const int rowg = tid >> 4;

    auto fillA = [&](int buf, int t) {
        char* bbp = smem + (size_t)buf * 49152;
        const int dcol = kbase + t * 64 + d4g;
        float4 w4[4];
        #pragma unroll
        for (int j = 0; j < 4; j++)
            w4[j] = __ldg(reinterpret_cast<const float4*>(cw + (dcol + j) * 4));
        const float4 b4 = __ldg(reinterpret_cast<const float4*>(cb + dcol));
        const float bbv[4] = {b4.x, b4.y, b4.z, b4.w};

        #pragma unroll
        for (int p = 0; p < 2; p++) {
            const int lrow = rowg * 8 + p * 4;
            const int grow = bm + lrow;
            const int lpos = grow & (L_ - 1);
            const float* base = xz + (size_t)grow * (2 * D_INNER) + dcol;
            float4 v[7];
            #pragma unroll
            for (int k = 0; k < 3; k++)
                v[k] = (lpos - 3 + k >= 0)
                     ? *reinterpret_cast<const float4*>(base + (ptrdiff_t)(k - 3) * 2 * D_INNER)
                     : make_float4(0.f, 0.f, 0.f, 0.f);
            #pragma unroll
            for (int k = 3; k < 7; k++)
                v[k] = *reinterpret_cast<const float4*>(base + (ptrdiff_t)(k - 3) * 2 * D_INNER);

            #pragma unroll
            for (int i = 0; i < 4; i++) {
                const float* e0 = &v[i + 0].x;
                const float* e1 = &v[i + 1].x;
                const float* e2 = &v[i + 2].x;
                const float* e3 = &v[i + 3].x;
                float4 r;
                float* rr = &r.x;
                #pragma unroll
                for (int j = 0; j < 4; j++) {
                    float acc = bbv[j];
                    acc = fmaf(w4[j].x, e0[j], acc);
                    acc = fmaf(w4[j].y, e1[j], acc);
                    acc = fmaf(w4[j].z, e2[j], acc);
                    acc = fmaf(w4[j].w, e3[j], acc);
                    rr[j] = act_silu(acc);
                }
                *reinterpret_cast<float4*>(&xc[(size_t)(grow + i) * D_INNER + dcol]) = r;
                uint2 hh, ll;
                split4(r, hh, ll);
                uint32_t off = (uint32_t)((lrow + i) * 128 + d4g * 2);
                uint32_t sw = off ^ ((off >> 3) & 0x70);
                *reinterpret_cast<uint2*>(bbp + sw) = hh;
                *reinterpret_cast<uint2*>(bbp + 16384 + sw) = ll;
            }
        }
    };

    const int l7 = lane & 7;
    const uint32_t xorv = (uint32_t)l7 << 4;
    const int a_row = wm * 32 + l7 + ((lane >> 3) & 1) * 8;
    const uint32_t a_kb = (uint32_t)((lane >> 4) & 1) * 16;
    const int b_row = wn * 32 + ((lane >> 4) & 1) * 8 + l7;
    const uint32_t b_kb = (uint32_t)((lane >> 3) & 1) * 16;

    float acc[2][4][4];
    #pragma unroll
    for (int i = 0; i < 2; i++)
        #pragma unroll
        for (int j = 0; j < 4; j++)
            #pragma unroll
            for (int r = 0; r < 4; r++) acc[i][j][r] = 0.f;

    fillW(0, 0);
    CP_COMMIT();
    fillA(0, 0);

    #pragma unroll
    for (int t = 0; t < 2; t++) {
        if (t == 0) {
            fillW(1, 1);
            CP_COMMIT();
            CP_WAIT(1);
        } else {
            CP_WAIT(0);
        }
        __syncthreads();

        const uint32_t bb = sbase + (uint32_t)t * 49152;
        #pragma unroll
        for (int kk = 0; kk < 4; kk++) {
            const uint32_t koff_a = ((uint32_t)(kk * 32) + a_kb) ^ xorv;
            const uint32_t koff_b = ((uint32_t)(kk * 32) + b_kb) ^ xorv;
            uint32_t ah[2][4], al[2][4], bh[2][4], bl[2][4];
            #pragma unroll
            for (int i = 0; i < 2; i++) {
                uint32_t ad = bb + (uint32_t)((a_row + i * 16) * 128) + koff_a;
                ldsm_x4(ah[i], ad);
                ldsm_x4(al[i], ad + 16384);
            }
            #pragma unroll
            for (int jj = 0; jj < 2; jj++) {
                uint32_t bd = bb + 32768 + (uint32_t)((b_row + jj * 16) * 128) + koff_b;
                ldsm_x4(bh[jj], bd);
                ldsm_x4(bl[jj], bd + 8192);
            }
            #pragma unroll
            for (int i = 0; i < 2; i++)
                #pragma unroll
                for (int j = 0; j < 4; j++)
                    mma16816(acc[i][j], ah[i], &bh[j >> 1][(j & 1) * 2]);
            #pragma unroll
            for (int i = 0; i < 2; i++)
                #pragma unroll
                for (int j = 0; j < 4; j++)
                    mma16816(acc[i][j], ah[i], &bl[j >> 1][(j & 1) * 2]);
            #pragma unroll
            for (int i = 0; i < 2; i++)
                #pragma unroll
                for (int j = 0; j < 4; j++)
                    mma16816(acc[i][j], al[i], &bh[j >> 1][(j & 1) * 2]);
        }
        __syncthreads();
        if (t == 0) fillA(1, 1);
    }

    const int g = lane >> 2;
    const int t4 = lane & 3;
    #pragma unroll
    for (int i = 0; i < 2; i++) {
        const int r0 = bm + wm * 32 + i * 16 + g;
        const int r1 = r0 + 8;
        #pragma unroll
        for (int j = 0; j < 4; j++) {
            const int col = wn * 32 + j * 8 + t4 * 2;
            epi_store(C, nullptr, nullptr, nullptr, 0, 64, r0, r1, col, acc[i][j]);
        }
    }
}

// reduce x_proj split-K partials -> xdbl fp32 + planes
__global__ void reduce_x(const float* __restrict__ part, float* __restrict__ out,
                         __nv_bfloat16* __restrict__ oh, __nv_bfloat16* __restrict__ ol)
{
    int i = blockIdx.x * blockDim.x + threadIdx.x;
    if (i >= ML * 16) return;
    float4 a = reinterpret_cast<const float4*>(part)[i];
    #pragma unroll
    for (int z = 1; z < XKS; z++) {
        float4 b = reinterpret_cast<const float4*>(part + (size_t)z * ML * 64)[i];
        a.x += b.x; a.y += b.y; a.z += b.z; a.w += b.w;
    }
    reinterpret_cast<float4*>(out)[i] = a;
    uint2 hh, ll;
    split4(a, hh, ll);
    reinterpret_cast<uint2*>(oh)[i] = hh;
    reinterpret_cast<uint2*>(ol)[i] = ll;
}

// =====================================================================
// Chunked selective scan: emits y planes (mid layers) OR per-chunk
// y-sums for the pushed-through mean (last layer).
// =====================================================================
__global__ __launch_bounds__(256) void scan_kernel(
    const float* __restrict__ dt, const float* __restrict__ xc,
    const float* __restrict__ xdbl, const float* __restrict__ xz,
    const float* __restrict__ A_log, const float* __restrict__ Dm,
    __nv_bfloat16* __restrict__ yh, __nv_bfloat16* __restrict__ yl,
    float* __restrict__ ympart)
{
    const int tid = threadIdx.x;
    const int dl = tid & 31;
    const int c = tid >> 5;
    const int d = blockIdx.x * 32 + dl;
    const int b = blockIdx.y;

    __shared__ float s_h[NCH][32][D_STATE];
    __shared__ float s_sd[NCH][32];
    __shared__ float s_hin[NCH][32][D_STATE];

    float Av[D_STATE];
    #pragma unroll
    for (int s = 0; s < D_STATE; s++) Av[s] = -__expf(__ldg(&A_log[d * D_STATE + s]));
    const float Av0 = Av[0];
    int fastl = 1;
    #pragma unroll
    for (int s = 1; s < D_STATE; s++) {
        float tgt = (s + 1) * Av0;
        fastl &= (fabsf(Av[s] - tgt) <= 1e-4f * fabsf(tgt)) ? 1 : 0;
    }
    const int fast = __syncthreads_and(fastl);

    const size_t rowb = (size_t)b * L_ + c * CHL;

    // Phase A: partial scan from zero
    float h[D_STATE];
    #pragma unroll
    for (int s = 0; s < D_STATE; s++) h[s] = 0.f;
    float sumdt = 0.f;

    for (int i = 0; i < CHL; i++) {
        const size_t row = rowb + i;
        const float dtv = __ldg(&dt[row * D_INNER + d]);
        const float xv  = __ldg(&xc[row * D_INNER + d]);
        sumdt += dtv;
        const float p = dtv * xv;
        const float4* bp = reinterpret_cast<const float4*>(xdbl + row * 64 + 32);
        float4 b0 = __ldg(bp + 0), b1 = __ldg(bp + 1), b2 = __ldg(bp + 2), b3 = __ldg(bp + 3);
        const float Bv[16] = {b0.x, b0.y, b0.z, b0.w, b1.x, b1.y, b1.z, b1.w,
                              b2.x, b2.y, b2.z, b2.w, b3.x, b3.y, b3.z, b3.w};
        if (fast) {
            const float q1 = __expf(dtv * Av0);
            const float q2 = q1 * q1, q3 = q2 * q1, q4 = q2 * q2;
            const float q5 = q4 * q1, q6 = q4 * q2, q7 = q4 * q3, q8 = q4 * q4;
            const float dA[16] = {q1, q2, q3, q4, q5, q6, q7, q8,
                                  q8*q1, q8*q2, q8*q3, q8*q4, q8*q5, q8*q6, q8*q7, q8*q8};
            #pragma unroll
            for (int s = 0; s < D_STATE; s++)
                h[s] = fmaf(dA[s], h[s], p * Bv[s]);
        } else {
            #pragma unroll
            for (int s = 0; s < D_STATE; s++)
                h[s] = fmaf(__expf(dtv * Av[s]), h[s], p * Bv[s]);
        }
    }
    #pragma unroll
    for (int s = 0; s < D_STATE; s++) s_h[c][dl][s] = h[s];
    s_sd[c][dl] = sumdt;
    __syncthreads();

    // Phase B: serial prefix over chunks
    #pragma unroll
    for (int it = 0; it < 2; it++) {
        const int item = tid * 2 + it;
        const int pdl = item >> 4;
        const int ps = item & 15;
        const float av = -__expf(__ldg(&A_log[(blockIdx.x * 32 + pdl) * D_STATE + ps]));
        float hin = 0.f;
        s_hin[0][pdl][ps] = 0.f;
        for (int cc = 1; cc < NCH; cc++) {
            const float P = __expf(av * s_sd[cc - 1][pdl]);
            hin = fmaf(P, hin, s_h[cc - 1][pdl][ps]);
            s_hin[cc][pdl][ps] = hin;
        }
    }
    __syncthreads();

    // Phase C: re-run with incoming state, emit y (planes or chunk-sum)
    #pragma unroll
    for (int s = 0; s < D_STATE; s++) h[s] = s_hin[c][dl][s];
    const float Dd = __ldg(&Dm[d]);
    float ysum = 0.f;

    for (int i = 0; i < CHL; i++) {
        const size_t row = rowb + i;
        const float dtv = __ldg(&dt[row * D_INNER + d]);
        const float xv  = __ldg(&xc[row * D_INNER + d]);
        const float zv  = __ldg(&xz[row * 2 * D_INNER + D_INNER + d]);
        const float p = dtv * xv;
        const float4* bp = reinterpret_cast<const float4*>(xdbl + row * 64 + 32);
        float4 b0 = __ldg(bp + 0), b1 = __ldg(bp + 1), b2 = __ldg(bp + 2), b3 = __ldg(bp + 3);
        float4 c0 = __ldg(bp + 4), c1 = __ldg(bp + 5), c2 = __ldg(bp + 6), c3 = __ldg(bp + 7);
        const float Bv[16] = {b0.x, b0.y, b0.z, b0.w, b1.x, b1.y, b1.z, b1.w,
                              b2.x, b2.y, b2.z, b2.w, b3.x, b3.y, b3.z, b3.w};
        const float Cv[16] = {c0.x, c0.y, c0.z, c0.w, c1.x, c1.y, c1.z, c1.w,
                              c2.x, c2.y, c2.z, c2.w, c3.x, c3.y, c3.z, c3.w};
        float acc0 = 0.f, acc1 = 0.f;
        if (fast) {
            const float q1 = __expf(dtv * Av0);
            const float q2 = q1 * q1, q3 = q2 * q1, q4 = q2 * q2;
            const float q5 = q4 * q1, q6 = q4 * q2, q7 = q4 * q3, q8 = q4 * q4;
            const float dA[16] = {q1, q2, q3, q4, q5, q6, q7, q8,
                                  q8*q1, q8*q2, q8*q3, q8*q4, q8*q5, q8*q6, q8*q7, q8*q8};
            #pragma unroll
            for (int s = 0; s < D_STATE; s++) {
                float hs = fmaf(dA[s], h[s], p * Bv[s]);
                h[s] = hs;
                if (s & 1) acc1 = fmaf(hs, Cv[s], acc1);
                else       acc0 = fmaf(hs, Cv[s], acc0);
            }
        } else {
            #pragma unroll
            for (int s = 0; s < D_STATE; s++) {
                float hs = fmaf(__expf(dtv * Av[s]), h[s], p * Bv[s]);
                h[s] = hs;
                if (s & 1) acc1 = fmaf(hs, Cv[s], acc1);
                else       acc0 = fmaf(hs, Cv[s], acc0);
            }
        }
        float yv = fmaf(xv, Dd, acc0 + acc1) * act_silu(zv);
        if (yh) {
            __nv_bfloat16 hb = __float2bfloat16(yv);
            yh[row * D_INNER + d] = hb;
            yl[row * D_INNER + d] = __float2bfloat16(yv - __bfloat162float(hb));
        } else {
            ysum += yv;
        }
    }
    if (ympart)
        ympart[((size_t)c * B_ + b) * D_INNER + d] = ysum;
}

// =====================================================================
// Final: reduce y chunk-sums -> mean, out_proj (fp32 dot), classifier.
// Grid = B_, 512 threads.
// =====================================================================
__global__ __launch_bounds__(512) void mean_cls_last(
    const float* __restrict__ ympart,
    const float* __restrict__ outw,    // last-layer out_proj_w [512][1024] fp32
    const float* __restrict__ w1, const float* __restrict__ b1,
    const float* __restrict__ w2, const float* __restrict__ b2,
    float* __restrict__ out)
{
    const int b = blockIdx.x;
    const int t = threadIdx.x;
    __shared__ float ym[D_INNER];
    __shared__ float hm[D_MODEL];
    __shared__ float hid[64];

    #pragma unroll
    for (int d = t; d < D_INNER; d += 512) {
        float s = 0.f;
        #pragma unroll
        for (int c = 0; c < NCH; c++)
            s += ympart[((size_t)c * B_ + b) * D_INNER + d];
        ym[d] = s * (1.f / L_);
    }
    __syncthreads();

    // hm[t] = dot(ym, outw[t,:])
    {
        const float* wr = outw + (size_t)t * D_INNER;
        float a = 0.f;
        for (int k = 0; k < D_INNER; k += 4) {
            float4 w4 = __ldg(reinterpret_cast<const float4*>(wr + k));
            a = fmaf(ym[k + 0], w4.x, a);
            a = fmaf(ym[k + 1], w4.y, a);
            a = fmaf(ym[k + 2], w4.z, a);
            a = fmaf(ym[k + 3], w4.w, a);
        }
        hm[t] = a;
    }
    __syncthreads();

    if (t < 64) {
        float a = __ldg(&b1[t]);
        const float* wv = w1 + t * D_MODEL;
        for (int k = 0; k < D_MODEL; k += 4) {
            float4 ww = __ldg(reinterpret_cast<const float4*>(&wv[k]));
            a = fmaf(hm[k + 0], ww.x, a);
            a = fmaf(hm[k + 1], ww.y, a);
            a = fmaf(hm[k + 2], ww.z, a);
            a = fmaf(hm[k + 3], ww.w, a);
        }
        hid[t] = fmaxf(a, 0.f) * __ldg(&w2[t]);
    }
    __syncthreads();
    if (t == 0) {
        float s = __ldg(&b2[0]);
        #pragma unroll
        for (int u = 0; u < 64; u++) s += hid[u];
        out[b] = s;
    }
}

// ---------------- launch ----------------
extern "C" void kernel_launch(void* const* d_in, const int* in_sizes, int n_in,
                              void* d_out, int out_size)
{
    const float* x          = (const float*)d_in[0];
    const float* proj_in_w  = (const float*)d_in[1];
    const float* proj_in_b  = (const float*)d_in[2];
    const float* in_proj_w  = (const float*)d_in[3];
    const float* conv_w     = (const float*)d_in[4];
    const float* conv_b     = (const float*)d_in[5];
    const float* x_proj_w   = (const float*)d_in[6];
    const float* dt_proj_w  = (const float*)d_in[7];
    const float* dt_proj_b  = (const float*)d_in[8];
    const float* A_log      = (const float*)d_in[9];
    const float* Dm         = (const float*)d_in[10];
    const float* out_proj_w = (const float*)d_in[11];
    const float* cls_w1     = (const float*)d_in[12];
    const float* cls_b1     = (const float*)d_in[13];
    const float* cls_w2     = (const float*)d_in[14];
    const float* cls_b2     = (const float*)d_in[15];

    void* p;
    cudaGetSymbolAddress(&p, g_xz);     float* xz     = (float*)p;
    cudaGetSymbolAddress(&p, g_xc);     float* xc     = (float*)p;
    cudaGetSymbolAddress(&p, g_xdbl);   float* xdbl   = (float*)p;
    cudaGetSymbolAddress(&p, g_xpart);  float* xpart  = (float*)p;
    cudaGetSymbolAddress(&p, g_dt);     float* dtb    = (float*)p;
    cudaGetSymbolAddress(&p, g_ympart); float* ympart = (float*)p;

    __nv_bfloat16 *xh, *xl, *piwh, *piwl, *inwh, *inwl, *outwh, *outwl;
    __nv_bfloat16 *xpwh, *xpwl, *dtwh, *dtwl, *hh, *hl, *xdblh, *xdbll, *yh, *yl;
    cudaGetSymbolAddress(&p, g_xh);    xh    = (__nv_bfloat16*)p;
    cudaGetSymbolAddress(&p, g_xl);    xl    = (__nv_bfloat16*)p;
    cudaGetSymbolAddress(&p, g_piwh);  piwh  = (__nv_bfloat16*)p;
    cudaGetSymbolAddress(&p, g_piwl);  piwl  = (__nv_bfloat16*)p;
    cudaGetSymbolAddress(&p, g_inwh);  inwh  = (__nv_bfloat16*)p;
    cudaGetSymbolAddress(&p, g_inwl);  inwl  = (__nv_bfloat16*)p;
    cudaGetSymbolAddress(&p, g_outwh); outwh = (__nv_bfloat16*)p;
    cudaGetSymbolAddress(&p, g_outwl); outwl = (__nv_bfloat16*)p;
    cudaGetSymbolAddress(&p, g_xpwh);  xpwh  = (__nv_bfloat16*)p;
    cudaGetSymbolAddress(&p, g_xpwl);  xpwl  = (__nv_bfloat16*)p;
    cudaGetSymbolAddress(&p, g_dtwh);  dtwh  = (__nv_bfloat16*)p;
    cudaGetSymbolAddress(&p, g_dtwl);  dtwl  = (__nv_bfloat16*)p;
    cudaGetSymbolAddress(&p, g_hh);    hh    = (__nv_bfloat16*)p;
    cudaGetSymbolAddress(&p, g_hl);    hl    = (__nv_bfloat16*)p;
    cudaGetSymbolAddress(&p, g_xdblh); xdblh = (__nv_bfloat16*)p;
    cudaGetSymbolAddress(&p, g_xdbll); xdbll = (__nv_bfloat16*)p;
    cudaGetSymbolAddress(&p, g_yh);    yh    = (__nv_bfloat16*)p;
    cudaGetSymbolAddress(&p, g_yl);    yl    = (__nv_bfloat16*)p;

    cudaFuncSetAttribute(gemm_mma_s, cudaFuncAttributeMaxDynamicSharedMemorySize, MMS_SMEM_BYTES);
    cudaFuncSetAttribute(conv_xproj_mma, cudaFuncAttributeMaxDynamicSharedMemorySize, MMS_SMEM_BYTES);

    // L1: all splits in one launch (layer-0 out_proj planes only)
    {
        int total = ML * D_IN / 4 + D_MODEL * D_IN / 4
                  + N_LAYERS * 2 * D_INNER * D_MODEL / 4 + D_MODEL * D_INNER / 4
                  + N_LAYERS * 64 * D_INNER / 4 + N_LAYERS * D_INNER * 8;
        cvt_all<<<(total + 255) / 256, 256>>>(x, xh, xl, proj_in_w, piwh, piwl,
                                              in_proj_w, inwh, inwl, out_proj_w, outwh, outwl,
                                              x_proj_w, xpwh, xpwl, dt_proj_w, dtwh, dtwl);
    }
    // L2: proj_in -> h planes (grid 8x32)
    gemm_mma_s<<<dim3(D_MODEL / 64, ML / 128), 256, MMS_SMEM_BYTES>>>(
        xh, xl, D_IN, piwh, piwl, D_IN, proj_in_b,
        nullptr, hh, hl, D_MODEL, D_IN, 0, 0);

    for (int l = 0; l < N_LAYERS; l++) {
        const size_t inw_off  = (size_t)l * 2 * D_INNER * D_MODEL;
        const float* cw    = conv_w     + (size_t)l * D_INNER * D_CONV;
        const float* cb    = conv_b     + (size_t)l * D_INNER;
        const float* dt_b  = dt_proj_b  + (size_t)l * D_INNER;
        const float* Al    = A_log      + (size_t)l * D_INNER * D_STATE;
        const float* Dl    = Dm         + (size_t)l * D_INNER;
        const bool last = (l == N_LAYERS - 1);

        // xz = h @ in_w^T  (grid 32x32 = 1024 CTAs)
        gemm_mma_s<<<dim3(2 * D_INNER / 64, ML / 128), 256, MMS_SMEM_BYTES>>>(
            hh, hl, D_MODEL, inwh + inw_off, inwl + inw_off, D_MODEL,
            nullptr, xz, nullptr, nullptr, 2 * D_INNER, D_MODEL, 0, 0);

        // fused conv + x_proj split-K (grid 1x32x8)
        conv_xproj_mma<<<dim3(1, ML / 128, XKS), 256, MMS_SMEM_BYTES>>>(
            xz, cw, cb, xc,
            xpwh + (size_t)l * 64 * D_INNER, xpwl + (size_t)l * 64 * D_INNER,
            xpart);
        reduce_x<<<(ML * 16 + 255) / 256, 256>>>(xpart, xdbl, xdblh, xdbll);

        // dt = softplus(xdbl @ dtw_pad^T + b)  (grid 16x32, K=64)
        gemm_mma_s<<<dim3(D_INNER / 64, ML / 128), 256, MMS_SMEM_BYTES>>>(
            xdblh, xdbll, 64,
            dtwh + (size_t)l * D_INNER * 64, dtwl + (size_t)l * D_INNER * 64, 64,
            dt_b, dtb, nullptr, nullptr, D_INNER, 64, 1, 0);

        // scan: mid layers -> y planes; last layer -> chunked y-sums
        scan_kernel<<<dim3(D_INNER / 32, B_), 256>>>(
            dtb, xc, xdbl, xz, Al, Dl,
            last ? nullptr : yh, last ? nullptr : yl,
            last ? ympart : nullptr);

        if (!last) {
            // out_proj (grid 8x32) -> next h planes
            gemm_mma_s<<<dim3(D_MODEL / 64, ML / 128), 256, MMS_SMEM_BYTES>>>(
                yh, yl, D_INNER, outwh, outwl, D_INNER,
                nullptr, nullptr, hh, hl, D_MODEL, D_INNER, 0, 0);
        }
    }

    // final: mean(y) @ out_w^T -> classifier
    mean_cls_last<<<B_, 512>>>(
        ympart, out_proj_w + (size_t)(N_LAYERS - 1) * D_MODEL * D_INNER,
        cls_w1, cls_b1, cls_w2, cls_b2, (float*)d_out);
}

// round 15
// speedup vs baseline: 1.2063x; 1.2063x over previous
#include <cuda_runtime.h>
#include <cuda_fp16.h>
#include <cstdint>

// ---------------- model dims ----------------
#define B_    8
#define L_    512
#define D_IN  128
#define D_MODEL 512
#define N_LAYERS 2
#define D_STATE 16
#define D_CONV  4
#define D_INNER 1024
#define DT_RANK 32
#define ML (B_ * L_)
#define XKS 8                      // split-K / d-slice factor for fused conv+x_proj
#define NCH 8                      // scan chunks over L
#define CHL (L_ / NCH)             // 64 steps per chunk

// ---------------- scratch (fp32) ----------------
__device__ float g_ha[ML * D_MODEL];
__device__ float g_xz[ML * 2 * D_INNER];
__device__ float g_xc[ML * D_INNER];
__device__ float g_xdbl[ML * 64];
__device__ float g_xpart[XKS * ML * 64];
__device__ float g_dt[ML * D_INNER];

// fp16 planes: activations single (q), weights dual (h/l)
__device__ __align__(16) __half g_xq[ML * D_IN];
__device__ __align__(16) __half g_piwh[D_MODEL * D_IN];
__device__ __align__(16) __half g_piwl[D_MODEL * D_IN];
__device__ __align__(16) __half g_inwh[N_LAYERS * 2 * D_INNER * D_MODEL];
__device__ __align__(16) __half g_inwl[N_LAYERS * 2 * D_INNER * D_MODEL];
__device__ __align__(16) __half g_outwh[N_LAYERS * D_MODEL * D_INNER];
__device__ __align__(16) __half g_outwl[N_LAYERS * D_MODEL * D_INNER];
__device__ __align__(16) __half g_xpwh[N_LAYERS * 64 * D_INNER];
__device__ __align__(16) __half g_xpwl[N_LAYERS * 64 * D_INNER];
__device__ __align__(16) __half g_dtwh[N_LAYERS * D_INNER * 64];   // padded K 32->64
__device__ __align__(16) __half g_dtwl[N_LAYERS * D_INNER * 64];
__device__ __align__(16) __half g_hq[ML * D_MODEL];
__device__ __align__(16) __half g_xdblq[ML * 64];
__device__ __align__(16) __half g_yq[ML * D_INNER];

__device__ __forceinline__ float act_silu(float v) { return v / (1.f + __expf(-v)); }
__device__ __forceinline__ float act_softplus(float v) { return (v > 20.f) ? v : log1pf(__expf(v)); }

// =====================================================================
// PTX helpers
// =====================================================================
__device__ __forceinline__ void ldsm_x4(uint32_t* r, uint32_t addr) {
    asm volatile("ldmatrix.sync.aligned.m8n8.x4.shared.b16 {%0,%1,%2,%3}, [%4];"
                 : "=r"(r[0]), "=r"(r[1]), "=r"(r[2]), "=r"(r[3]) : "r"(addr));
}
__device__ __forceinline__ void mma16816(float* c, const uint32_t* a, const uint32_t* b) {
    asm volatile(
        "mma.sync.aligned.m16n8k16.row.col.f32.f16.f16.f32 "
        "{%0,%1,%2,%3}, {%4,%5,%6,%7}, {%8,%9}, {%0,%1,%2,%3};"
        : "+f"(c[0]), "+f"(c[1]), "+f"(c[2]), "+f"(c[3])
        : "r"(a[0]), "r"(a[1]), "r"(a[2]), "r"(a[3]), "r"(b[0]), "r"(b[1]));
}
__device__ __forceinline__ void cp16(uint32_t dst, const void* src) {
    asm volatile("cp.async.cg.shared.global [%0], [%1], 16;" :: "r"(dst), "l"(src));
}
#define CP_COMMIT() asm volatile("cp.async.commit_group;" ::: "memory")
#define CP_WAIT(n)  asm volatile("cp.async.wait_group %0;" :: "n"(n) : "memory")

__device__ __forceinline__ uint32_t h2_bits(__half2 v) {
    return *reinterpret_cast<const uint32_t*>(&v);
}
// float4 -> 4 fp16 (single plane)
__device__ __forceinline__ uint2 quant4(float4 v) {
    __half2 a = __floats2half2_rn(v.x, v.y);
    __half2 b = __floats2half2_rn(v.z, v.w);
    return make_uint2(h2_bits(a), h2_bits(b));
}
// float4 -> fp16 hi/lo dual planes
__device__ __forceinline__ void wsplit4(float4 v, uint2& h, uint2& l) {
    __half2 h0 = __floats2half2_rn(v.x, v.y);
    __half2 h1 = __floats2half2_rn(v.z, v.w);
    __half2 l0 = __floats2half2_rn(v.x - __low2float(h0), v.y - __high2float(h0));
    __half2 l1 = __floats2half2_rn(v.z - __low2float(h1), v.w - __high2float(h1));
    h = make_uint2(h2_bits(h0), h2_bits(h1));
    l = make_uint2(h2_bits(l0), h2_bits(l1));
}

// ---------------- all conversions in ONE launch ----------------
__global__ void cvt_all(const float* __restrict__ x,    __half* xq,
                        const float* __restrict__ piw,  __half* piwh, __half* piwl,
                        const float* __restrict__ inw,  __half* inwh, __half* inwl,
                        const float* __restrict__ outw, __half* outwh, __half* outwl,
                        const float* __restrict__ xpw,  __half* xpwh, __half* xpwl,
                        const float* __restrict__ dtw,  __half* dtwh, __half* dtwl)
{
    int i = blockIdx.x * blockDim.x + threadIdx.x;
    const int n_x   = ML * D_IN / 4;
    const int n_piw = D_MODEL * D_IN / 4;
    const int n_in  = N_LAYERS * 2 * D_INNER * D_MODEL / 4;
    const int n_out = N_LAYERS * D_MODEL * D_INNER / 4;
    const int n_xp  = N_LAYERS * 64 * D_INNER / 4;
    const int n_dt  = N_LAYERS * D_INNER * 8;
    if (i < n_x) {
        reinterpret_cast<uint2*>(xq)[i] = quant4(reinterpret_cast<const float4*>(x)[i]);
        return;
    }
    const float* src; __half *h, *l; int si, di;
    if ((i -= n_x) < n_piw) { src = piw; h = piwh; l = piwl; si = i; di = i; }
    else if ((i -= n_piw) < n_in) { src = inw; h = inwh; l = inwl; si = i; di = i; }
    else if ((i -= n_in) < n_out) { src = outw; h = outwh; l = outwl; si = i; di = i; }
    else if ((i -= n_out) < n_xp) { src = xpw; h = xpwh; l = xpwl; si = i; di = i; }
    else if ((i -= n_xp) < n_dt) {
        int row = i >> 3, q = i & 7;
        src = dtw; h = dtwh; l = dtwl;
        si = row * 8 + q;     // 32 floats per row = 8 quads
        di = row * 16 + q;    // padded 64 halves per row = 16 quads
    }
    else return;
    uint2 hh, ll;
    wsplit4(reinterpret_cast<const float4*>(src)[si], hh, ll);
    reinterpret_cast<uint2*>(h)[di] = hh;
    reinterpret_cast<uint2*>(l)[di] = ll;
}

// ---------------- common epilogue store ----------------
__device__ __forceinline__ void epi_store(
    float* C, __half* Cq,
    const float* bias, int act, int ldc,
    int r0, int r1, int col, const float* a)
{
    const float b0 = bias ? __ldg(&bias[col]) : 0.f;
    const float b1 = bias ? __ldg(&bias[col + 1]) : 0.f;
    float2 v0 = make_float2(a[0] + b0, a[1] + b1);
    float2 v1 = make_float2(a[2] + b0, a[3] + b1);
    if (act == 1) {
        v0.x = act_softplus(v0.x); v0.y = act_softplus(v0.y);
        v1.x = act_softplus(v1.x); v1.y = act_softplus(v1.y);
    }
    if (C) {
        *reinterpret_cast<float2*>(&C[(size_t)r0 * ldc + col]) = v0;
        *reinterpret_cast<float2*>(&C[(size_t)r1 * ldc + col]) = v1;
    }
    if (Cq) {
        __half2 p0 = __floats2half2_rn(v0.x, v0.y);
        __half2 p1 = __floats2half2_rn(v1.x, v1.y);
        *reinterpret_cast<uint32_t*>(&Cq[(size_t)r0 * ldc + col]) = h2_bits(p0);
        *reinterpret_cast<uint32_t*>(&Cq[(size_t)r1 * ldc + col]) = h2_bits(p1);
    }
}

// =====================================================================
// gemm_f16: CTA 128x64, 256 thr (8 warps 4x2), warp 32x32, K-chunk 64.
// A single fp16 plane; W dual fp16 planes; 2 MMA terms.
// Buffer: Aq @0 (16K), Wh @16K (8K), Wl @24K (8K); double 2x32KB; 2 CTA/SM.
// =====================================================================
#define MMS_SMEM_BYTES 65536

__global__ __launch_bounds__(256, 2) void gemm_f16(
    const __half* __restrict__ Aq, int lda,
    const __half* __restrict__ Wh, const __half* __restrict__ Wl, int ldw,
    const float* __restrict__ bias, float* __restrict__ C,
    __half* __restrict__ Cq,
    int ldc, int K, int act, size_t zstride)
{
    extern __shared__ char smem[];
    const uint32_t sbase = (uint32_t)__cvta_generic_to_shared(smem);
    const int tid = threadIdx.x;
    const int lane = tid & 31;
    const int wid = tid >> 5;
    const int wm = wid & 3;
    const int wn = wid >> 2;
    const int bm = blockIdx.y * 128;
    const int bn = blockIdx.x * 64;
    {
        const int z = blockIdx.z;
        Aq += (size_t)z * K;
        Wh += (size_t)z * K; Wl += (size_t)z * K;
        C  += (size_t)z * zstride;
    }

    const int rf = tid >> 3;
    const int sf = tid & 7;
    const uint32_t swb = (uint32_t)(rf * 128 + sf * 16) ^ (((uint32_t)rf & 7u) << 4);

    auto fill = [&](int buf, int k0) {
        const uint32_t bb = sbase + (uint32_t)buf * 32768;
        #pragma unroll
        for (int u = 0; u < 4; u++) {                 // A: 128 rows
            const int row = rf + u * 32;
            const uint32_t sw = swb + (uint32_t)(u * 4096);
            cp16(bb + sw, Aq + (size_t)(bm + row) * lda + k0 + sf * 8);
        }
        #pragma unroll
        for (int u = 0; u < 2; u++) {                 // W: 64 rows x 2 planes
            const int row = rf + u * 32;
            const uint32_t sw = swb + (uint32_t)(u * 4096);
            const size_t go = (size_t)(bn + row) * ldw + k0 + sf * 8;
            cp16(bb + 16384 + sw, Wh + go);
            cp16(bb + 24576 + sw, Wl + go);
        }
    };

    const int l7 = lane & 7;
    const uint32_t xorv = (uint32_t)l7 << 4;
    const int a_row = wm * 32 + l7 + ((lane >> 3) & 1) * 8;
    const uint32_t a_kb = (uint32_t)((lane >> 4) & 1) * 16;
    const int b_row = wn * 32 + ((lane >> 4) & 1) * 8 + l7;
    const uint32_t b_kb = (uint32_t)((lane >> 3) & 1) * 16;

    float acc[2][4][4];
    #pragma unroll
    for (int i = 0; i < 2; i++)
        #pragma unroll
        for (int j = 0; j < 4; j++)
            #pragma unroll
            for (int r = 0; r < 4; r++) acc[i][j][r] = 0.f;

    const int nt = K / 64;

    fill(0, 0);
    CP_COMMIT();

    for (int t = 0; t < nt; t++) {
        const int buf = t & 1;
        if (t + 1 < nt) {
            fill(buf ^ 1, (t + 1) * 64);
            CP_COMMIT();
            CP_WAIT(1);
        } else {
            CP_WAIT(0);
        }
        __syncthreads();

        const uint32_t bb = sbase + (uint32_t)buf * 32768;
        #pragma unroll
        for (int kk = 0; kk < 4; kk++) {
            const uint32_t koff_a = ((uint32_t)(kk * 32) + a_kb) ^ xorv;
            const uint32_t koff_b = ((uint32_t)(kk * 32) + b_kb) ^ xorv;
            uint32_t ah[2][4], bh[2][4], bl[2][4];
            #pragma unroll
            for (int i = 0; i < 2; i++)
                ldsm_x4(ah[i], bb + (uint32_t)((a_row + i * 16) * 128) + koff_a);
            #pragma unroll
            for (int jj = 0; jj < 2; jj++) {
                uint32_t bd = bb + 16384 + (uint32_t)((b_row + jj * 16) * 128) + koff_b;
                ldsm_x4(bh[jj], bd);
                ldsm_x4(bl[jj], bd + 8192);
            }
            #pragma unroll
            for (int i = 0; i < 2; i++)
                #pragma unroll
                for (int j = 0; j < 4; j++)
                    mma16816(acc[i][j], ah[i], &bh[j >> 1][(j & 1) * 2]);
            #pragma unroll
            for (int i = 0; i < 2; i++)
                #pragma unroll
                for (int j = 0; j < 4; j++)
                    mma16816(acc[i][j], ah[i], &bl[j >> 1][(j & 1) * 2]);
        }
        __syncthreads();
    }

    const int g = lane >> 2;
    const int t4 = lane & 3;
    #pragma unroll
    for (int i = 0; i < 2; i++) {
        const int r0 = bm + wm * 32 + i * 16 + g;
        const int r1 = r0 + 8;
        #pragma unroll
        for (int j = 0; j < 4; j++) {
            const int col = bn + wn * 32 + j * 8 + t4 * 2;
            epi_store(C, Cq, bias, act, ldc, r0, r1, col, acc[i][j]);
        }
    }
}

// =====================================================================
// FUSED conv + x_proj GEMM (fp16 variant of r13 winner).
// A = conv output (computed in-kernel, single fp16 plane in smem, fp32 to xc);
// W dual planes via cp.async. Grid (1, ML/128, XKS), 2 K-chunks.
// =====================================================================
__global__ __launch_bounds__(256, 2) void conv_xproj_mma(
    const float* __restrict__ xz,
    const float* __restrict__ cw,
    const float* __restrict__ cb,
    float* __restrict__ xc,
    const __half* __restrict__ Wh,
    const __half* __restrict__ Wl,
    float* __restrict__ C)
{
    extern __shared__ char smem[];
    const uint32_t sbase = (uint32_t)__cvta_generic_to_shared(smem);
    const int tid = threadIdx.x;
    const int lane = tid & 31;
    const int wid = tid >> 5;
    const int wm = wid & 3;
    const int wn = wid >> 2;
    const int bm = blockIdx.y * 128;
    const int z = blockIdx.z;
    const int kbase = z * 128;
    C += (size_t)z * ML * 64;

    const int rf = tid >> 3;
    const int sf = tid & 7;
    const uint32_t swb = (uint32_t)(rf * 128 + sf * 16) ^ (((uint32_t)rf & 7u) << 4);

    auto fillW = [&](int buf, int t) {
        const uint32_t bb = sbase + (uint32_t)buf * 32768;
        const int k0 = kbase + t * 64;
        #pragma unroll
        for (int u = 0; u < 2; u++) {
            const int row = rf + u * 32;
            const uint32_t sw = swb + (uint32_t)(u * 4096);
            const size_t go = (size_t)row * D_INNER + k0 + sf * 8;
            cp16(bb + 16384 + sw, Wh + go);
            cp16(bb + 24576 + sw, Wl + go);
        }
    };

    const int d4g = (tid & 15) * 4;
    const int rowg = tid >> 4;

    auto fillA = [&](int buf, int t) {
        char* bbp = smem + (size_t)buf * 32768;
        const int dcol = kbase + t * 64 + d4g;
        float4 w4[4];
        #pragma unroll
        for (int j = 0; j < 4; j++)
            w4[j] = __ldg(reinterpret_cast<const float4*>(cw + (dcol + j) * 4));
        const float4 b4 = __ldg(reinterpret_cast<const float4*>(cb + dcol));
        const float bbv[4] = {b4.x, b4.y, b4.z, b4.w};

        #pragma unroll
        for (int p = 0; p < 2; p++) {
            const int lrow = rowg * 8 + p * 4;
            const int grow = bm + lrow;
            const int lpos = grow & (L_ - 1);
            const float* base = xz + (size_t)grow * (2 * D_INNER) + dcol;
            float4 v[7];
            #pragma unroll
            for (int k = 0; k < 3; k++)
                v[k] = (lpos - 3 + k >= 0)
                     ? *reinterpret_cast<const float4*>(base + (ptrdiff_t)(k - 3) * 2 * D_INNER)
                     : make_float4(0.f, 0.f, 0.f, 0.f);
            #pragma unroll
            for (int k = 3; k < 7; k++)
                v[k] = *reinterpret_cast<const float4*>(base + (ptrdiff_t)(k - 3) * 2 * D_INNER);

            #pragma unroll
            for (int i = 0; i < 4; i++) {
                const float* e0 = &v[i + 0].x;
                const float* e1 = &v[i + 1].x;
                const float* e2 = &v[i + 2].x;
                const float* e3 = &v[i + 3].x;
                float4 r;
                float* rr = &r.x;
                #pragma unroll
                for (int j = 0; j < 4; j++) {
                    float acc = bbv[j];
                    acc = fmaf(w4[j].x, e0[j], acc);
                    acc = fmaf(w4[j].y, e1[j], acc);
                    acc = fmaf(w4[j].z, e2[j], acc);
                    acc = fmaf(w4[j].w, e3[j], acc);
                    rr[j] = act_silu(acc);
                }
                *reinterpret_cast<float4*>(&xc[(size_t)(grow + i) * D_INNER + dcol]) = r;
                uint32_t off = (uint32_t)((lrow + i) * 128 + d4g * 2);
                uint32_t sw = off ^ ((off >> 3) & 0x70);
                *reinterpret_cast<uint2*>(bbp + sw) = quant4(r);
            }
        }
    };

    const int l7 = lane & 7;
    const uint32_t xorv = (uint32_t)l7 << 4;
    const int a_row = wm * 32 + l7 + ((lane >> 3) & 1) * 8;
    const uint32_t a_kb = (uint32_t)((lane >> 4) & 1) * 16;
    const int b_row = wn * 32 + ((lane >> 4) & 1) * 8 + l7;
    const uint32_t b_kb = (uint32_t)((lane >> 3) & 1) * 16;

    float acc[2][4][4];
    #pragma unroll
    for (int i = 0; i < 2; i++)
        #pragma unroll
        for (int j = 0; j < 4; j++)
            #pragma unroll
            for (int r = 0; r < 4; r++) acc[i][j][r] = 0.f;

    fillW(0, 0);
    CP_COMMIT();
    fillA(0, 0);

    #pragma unroll
    for (int t = 0; t < 2; t++) {
        if (t == 0) {
            fillW(1, 1);
            CP_COMMIT();
            CP_WAIT(1);
        } else {
            CP_WAIT(0);
        }
        __syncthreads();

        const uint32_t bb = sbase + (uint32_t)t * 32768;
        #pragma unroll
        for (int kk = 0; kk < 4; kk++) {
            const uint32_t koff_a = ((uint32_t)(kk * 32) + a_kb) ^ xorv;
            const uint32_t koff_b = ((uint32_t)(kk * 32) + b_kb) ^ xorv;
            uint32_t ah[2][4], bh[2][4], bl[2][4];
            #pragma unroll
            for (int i = 0; i < 2; i++)
                ldsm_x4(ah[i], bb + (uint32_t)((a_row + i * 16) * 128) + koff_a);
            #pragma unroll
            for (int jj = 0; jj < 2; jj++) {
                uint32_t bd = bb + 16384 + (uint32_t)((b_row + jj * 16) * 128) + koff_b;
                ldsm_x4(bh[jj], bd);
                ldsm_x4(bl[jj], bd + 8192);
            }
            #pragma unroll
            for (int i = 0; i < 2; i++)
                #pragma unroll
                for (int j = 0; j < 4; j++)
                    mma16816(acc[i][j], ah[i], &bh[j >> 1][(j & 1) * 2]);
            #pragma unroll
            for (int i = 0; i < 2; i++)
                #pragma unroll
                for (int j = 0; j < 4; j++)
                    mma16816(acc[i][j], ah[i], &bl[j >> 1][(j & 1) * 2]);
        }
        __syncthreads();
        if (t == 0) fillA(1, 1);
    }

    const int g = lane >> 2;
    const int t4 = lane & 3;
    #pragma unroll
    for (int i = 0; i < 2; i++) {
        const int r0 = bm + wm * 32 + i * 16 + g;
        const int r1 = r0 + 8;
        #pragma unroll
        for (int j = 0; j < 4; j++) {
            const int col = wn * 32 + j * 8 + t4 * 2;
            epi_store(C, nullptr, nullptr, 0, 64, r0, r1, col, acc[i][j]);
        }
    }
}

// reduce x_proj split-K partials -> xdbl fp32 + fp16 plane
__global__ void reduce_x(const float* __restrict__ part, float* __restrict__ out,
                         __half* __restrict__ oq)
{
    int i = blockIdx.x * blockDim.x + threadIdx.x;
    if (i >= ML * 16) return;
    float4 a = reinterpret_cast<const float4*>(part)[i];
    #pragma unroll
    for (int z = 1; z < XKS; z++) {
        float4 b = reinterpret_cast<const float4*>(part + (size_t)z * ML * 64)[i];
        a.x += b.x; a.y += b.y; a.z += b.z; a.w += b.w;
    }
    reinterpret_cast<float4*>(out)[i] = a;
    reinterpret_cast<uint2*>(oq)[i] = quant4(a);
}

// =====================================================================
// Chunked selective scan (r11/r13 WINNER; y emitted as single fp16 plane)
// =====================================================================
__global__ __launch_bounds__(256) void scan_kernel(
    const float* __restrict__ dt, const float* __restrict__ xc,
    const float* __restrict__ xdbl, const float* __restrict__ xz,
    const float* __restrict__ A_log, const float* __restrict__ Dm,
    __half* __restrict__ yq)
{
    const int tid = threadIdx.x;
    const int dl = tid & 31;
    const int c = tid >> 5;
    const int d = blockIdx.x * 32 + dl;
    const int b = blockIdx.y;

    __shared__ float s_h[NCH][32][D_STATE];
    __shared__ float s_sd[NCH][32];
    __shared__ float s_hin[NCH][32][D_STATE];

    float Av[D_STATE];
    #pragma unroll
    for (int s = 0; s < D_STATE; s++) Av[s] = -__expf(__ldg(&A_log[d * D_STATE + s]));
    const float Av0 = Av[0];
    int fastl = 1;
    #pragma unroll
    for (int s = 1; s < D_STATE; s++) {
        float tgt = (s + 1) * Av0;
        fastl &= (fabsf(Av[s] - tgt) <= 1e-4f * fabsf(tgt)) ? 1 : 0;
    }
    const int fast = __syncthreads_and(fastl);

    const size_t rowb = (size_t)b * L_ + c * CHL;

    // Phase A: partial scan from zero
    float h[D_STATE];
    #pragma unroll
    for (int s = 0; s < D_STATE; s++) h[s] = 0.f;
    float sumdt = 0.f;

    for (int i = 0; i < CHL; i++) {
        const size_t row = rowb + i;
        const float dtv = __ldg(&dt[row * D_INNER + d]);
        const float xv  = __ldg(&xc[row * D_INNER + d]);
        sumdt += dtv;
        const float p = dtv * xv;
        const float4* bp = reinterpret_cast<const float4*>(xdbl + row * 64 + 32);
        float4 b0 = __ldg(bp + 0), b1 = __ldg(bp + 1), b2 = __ldg(bp + 2), b3 = __ldg(bp + 3);
        const float Bv[16] = {b0.x, b0.y, b0.z, b0.w, b1.x, b1.y, b1.z, b1.w,
                              b2.x, b2.y, b2.z, b2.w, b3.x, b3.y, b3.z, b3.w};
        if (fast) {
            const float q1 = __expf(dtv * Av0);
            const float q2 = q1 * q1, q3 = q2 * q1, q4 = q2 * q2;
            const float q5 = q4 * q1, q6 = q4 * q2, q7 = q4 * q3, q8 = q4 * q4;
            const float dA[16] = {q1, q2, q3, q4, q5, q6, q7, q8,
                                  q8*q1, q8*q2, q8*q3, q8*q4, q8*q5, q8*q6, q8*q7, q8*q8};
            #pragma unroll
            for (int s = 0; s < D_STATE; s++)
                h[s] = fmaf(dA[s], h[s], p * Bv[s]);
        } else {
            #pragma unroll
            for (int s = 0; s < D_STATE; s++)
                h[s] = fmaf(__expf(dtv * Av[s]), h[s], p * Bv[s]);
        }
    }
    #pragma unroll
    for (int s = 0; s < D_STATE; s++) s_h[c][dl][s] = h[s];
    s_sd[c][dl] = sumdt;
    __syncthreads();

    // Phase B: serial prefix over chunks
    #pragma unroll
    for (int it = 0; it < 2; it++) {
        const int item = tid * 2 + it;
        const int pdl = item >> 4;
        const int ps = item & 15;
        const float av = -__expf(__ldg(&A_log[(blockIdx.x * 32 + pdl) * D_STATE + ps]));
        float hin = 0.f;
        s_hin[0][pdl][ps] = 0.f;
        for (int cc = 1; cc < NCH; cc++) {
            const float P = __expf(av * s_sd[cc - 1][pdl]);
            hin = fmaf(P, hin, s_h[cc - 1][pdl][ps]);
            s_hin[cc][pdl][ps] = hin;
        }
    }
    __syncthreads();

    // Phase C: re-run with incoming state, emit y
    #pragma unroll
    for (int s = 0; s < D_STATE; s++) h[s] = s_hin[c][dl][s];
    const float Dd = __ldg(&Dm[d]);

    for (int i = 0; i < CHL; i++) {
        const size_t row = rowb + i;
        const float dtv = __ldg(&dt[row * D_INNER + d]);
        const float xv  = __ldg(&xc[row * D_INNER + d]);
        const float zv  = __ldg(&xz[row * 2 * D_INNER + D_INNER + d]);
        const float p = dtv * xv;
        const float4* bp = reinterpret_cast<const float4*>(xdbl + row * 64 + 32);
        float4 b0 = __ldg(bp + 0), b1 = __ldg(bp + 1), b2 = __ldg(bp + 2), b3 = __ldg(bp + 3);
        float4 c0 = __ldg(bp + 4), c1 = __ldg(bp + 5), c2 = __ldg(bp + 6), c3 = __ldg(bp + 7);
        const float Bv[16] = {b0.x, b0.y, b0.z, b0.w, b1.x, b1.y, b1.z, b1.w,
                              b2.x, b2.y, b2.z, b2.w, b3.x, b3.y, b3.z, b3.w};
        const float Cv[16] = {c0.x, c0.y, c0.z, c0.w, c1.x, c1.y, c1.z, c1.w,
                              c2.x, c2.y, c2.z, c2.w, c3.x, c3.y, c3.z, c3.w};
        float acc0 = 0.f, acc1 = 0.f;
        if (fast) {
            const float q1 = __expf(dtv * Av0);
            const float q2 = q1 * q1, q3 = q2 * q1, q4 = q2 * q2;
            const float q5 = q4 * q1, q6 = q4 * q2, q7 = q4 * q3, q8 = q4 * q4;
            const float dA[16] = {q1, q2, q3, q4, q5, q6, q7, q8,
                                  q8*q1, q8*q2, q8*q3, q8*q4, q8*q5, q8*q6, q8*q7, q8*q8};
            #pragma unroll
            for (int s = 0; s < D_STATE; s++) {
                float hs = fmaf(dA[s], h[s], p * Bv[s]);
                h[s] = hs;
                if (s & 1) acc1 = fmaf(hs, Cv[s], acc1);
                else       acc0 = fmaf(hs, Cv[s], acc0);
            }
        } else {
            #pragma unroll
            for (int s = 0; s < D_STATE; s++) {
                float hs = fmaf(__expf(dtv * Av[s]), h[s], p * Bv[s]);
                h[s] = hs;
                if (s & 1) acc1 = fmaf(hs, Cv[s], acc1);
                else       acc0 = fmaf(hs, Cv[s], acc0);
            }
        }
        float yv = fmaf(xv, Dd, acc0 + acc1) * act_silu(zv);
        yq[row * D_INNER + d] = __float2half_rn(yv);
    }
}

// ---------------- fused mean + classifier head (r13 version) ----------------
__global__ __launch_bounds__(512) void mean_cls(
    const float* __restrict__ h,
    const float* __restrict__ w1, const float* __restrict__ b1,
    const float* __restrict__ w2, const float* __restrict__ b2,
    float* __restrict__ out)
{
    const int b = blockIdx.x;
    const int t = threadIdx.x;
    __shared__ float hm[D_MODEL];
    __shared__ float hid[64];

    float acc = 0.f;
    const float* p = h + (size_t)b * L_ * D_MODEL + t;
    #pragma unroll 8
    for (int l = 0; l < L_; l++) acc += p[(size_t)l * D_MODEL];
    hm[t] = acc * (1.f / L_);
    __syncthreads();

    if (t < 64) {
        float a = __ldg(&b1[t]);
        const float* wv = w1 + t * D_MODEL;
        for (int k = 0; k < D_MODEL; k += 4) {
            float4 ww = *reinterpret_cast<const float4*>(&wv[k]);
            a = fmaf(hm[k + 0], ww.x, a);
            a = fmaf(hm[k + 1], ww.y, a);
            a = fmaf(hm[k + 2], ww.z, a);
            a = fmaf(hm[k + 3], ww.w, a);
        }
        hid[t] = fmaxf(a, 0.f) * __ldg(&w2[t]);
    }
    __syncthreads();
    if (t == 0) {
        float s = __ldg(&b2[0]);
        #pragma unroll
        for (int u = 0; u < 64; u++) s += hid[u];
        out[b] = s;
    }
}

// ---------------- launch ----------------
extern "C" void kernel_launch(void* const* d_in, const int* in_sizes, int n_in,
                              void* d_out, int out_size)
{
    const float* x          = (const float*)d_in[0];
    const float* proj_in_w  = (const float*)d_in[1];
    const float* proj_in_b  = (const float*)d_in[2];
    const float* in_proj_w  = (const float*)d_in[3];
    const float* conv_w     = (const float*)d_in[4];
    const float* conv_b     = (const float*)d_in[5];
    const float* x_proj_w   = (const float*)d_in[6];
    const float* dt_proj_w  = (const float*)d_in[7];
    const float* dt_proj_b  = (const float*)d_in[8];
    const float* A_log      = (const float*)d_in[9];
    const float* Dm         = (const float*)d_in[10];
    const float* out_proj_w = (const float*)d_in[11];
    const float* cls_w1     = (const float*)d_in[12];
    const float* cls_b1     = (const float*)d_in[13];
    const float* cls_w2     = (const float*)d_in[14];
    const float* cls_b2     = (const float*)d_in[15];

    void* p;
    cudaGetSymbolAddress(&p, g_ha);    float* ha    = (float*)p;
    cudaGetSymbolAddress(&p, g_xz);    float* xz    = (float*)p;
    cudaGetSymbolAddress(&p, g_xc);    float* xc    = (float*)p;
    cudaGetSymbolAddress(&p, g_xdbl);  float* xdbl  = (float*)p;
    cudaGetSymbolAddress(&p, g_xpart); float* xpart = (float*)p;
    cudaGetSymbolAddress(&p, g_dt);    float* dtb   = (float*)p;

    __half *xq, *piwh, *piwl, *inwh, *inwl, *outwh, *outwl;
    __half *xpwh, *xpwl, *dtwh, *dtwl, *hq, *xdblq, *yq;
    cudaGetSymbolAddress(&p, g_xq);    xq    = (__half*)p;
    cudaGetSymbolAddress(&p, g_piwh);  piwh  = (__half*)p;
    cudaGetSymbolAddress(&p, g_piwl);  piwl  = (__half*)p;
    cudaGetSymbolAddress(&p, g_inwh);  inwh  = (__half*)p;
    cudaGetSymbolAddress(&p, g_inwl);  inwl  = (__half*)p;
    cudaGetSymbolAddress(&p, g_outwh); outwh = (__half*)p;
    cudaGetSymbolAddress(&p, g_outwl); outwl = (__half*)p;
    cudaGetSymbolAddress(&p, g_xpwh);  xpwh  = (__half*)p;
    cudaGetSymbolAddress(&p, g_xpwl);  xpwl  = (__half*)p;
    cudaGetSymbolAddress(&p, g_dtwh);  dtwh  = (__half*)p;
    cudaGetSymbolAddress(&p, g_dtwl);  dtwl  = (__half*)p;
    cudaGetSymbolAddress(&p, g_hq);    hq    = (__half*)p;
    cudaGetSymbolAddress(&p, g_xdblq); xdblq = (__half*)p;
    cudaGetSymbolAddress(&p, g_yq);    yq    = (__half*)p;

    cudaFuncSetAttribute(gemm_f16, cudaFuncAttributeMaxDynamicSharedMemorySize, MMS_SMEM_BYTES);
    cudaFuncSetAttribute(conv_xproj_mma, cudaFuncAttributeMaxDynamicSharedMemorySize, MMS_SMEM_BYTES);

    // L1: all conversions in one launch
    {
        int total = ML * D_IN / 4 + D_MODEL * D_IN / 4
                  + N_LAYERS * 2 * D_INNER * D_MODEL / 4 + N_LAYERS * D_MODEL * D_INNER / 4
                  + N_LAYERS * 64 * D_INNER / 4 + N_LAYERS * D_INNER * 8;
        cvt_all<<<(total + 255) / 256, 256>>>(x, xq, proj_in_w, piwh, piwl,
                                              in_proj_w, inwh, inwl, out_proj_w, outwh, outwl,
                                              x_proj_w, xpwh, xpwl, dt_proj_w, dtwh, dtwl);
    }
    // L2: proj_in -> h plane (grid 8x32)
    gemm_f16<<<dim3(D_MODEL / 64, ML / 128), 256, MMS_SMEM_BYTES>>>(
        xq, D_IN, piwh, piwl, D_IN, proj_in_b,
        nullptr, hq, D_MODEL, D_IN, 0, 0);

    for (int l = 0; l < N_LAYERS; l++) {
        const size_t inw_off  = (size_t)l * 2 * D_INNER * D_MODEL;
        const size_t outw_off = (size_t)l * D_MODEL * D_INNER;
        const float* cw    = conv_w     + (size_t)l * D_INNER * D_CONV;
        const float* cb    = conv_b     + (size_t)l * D_INNER;
        const float* dt_b  = dt_proj_b  + (size_t)l * D_INNER;
        const float* Al    = A_log      + (size_t)l * D_INNER * D_STATE;
        const float* Dl    = Dm         + (size_t)l * D_INNER;
        const bool last = (l == N_LAYERS - 1);

        // xz = h @ in_w^T  (grid 32x32 = 1024 CTAs)
        gemm_f16<<<dim3(2 * D_INNER / 64, ML / 128), 256, MMS_SMEM_BYTES>>>(
            hq, D_MODEL, inwh + inw_off, inwl + inw_off, D_MODEL,
            nullptr, xz, nullptr, 2 * D_INNER, D_MODEL, 0, 0);

        // fused conv + x_proj split-K (grid 1x32x8)
        conv_xproj_mma<<<dim3(1, ML / 128, XKS), 256, MMS_SMEM_BYTES>>>(
            xz, cw, cb, xc,
            xpwh + (size_t)l * 64 * D_INNER, xpwl + (size_t)l * 64 * D_INNER,
            xpart);
        reduce_x<<<(ML * 16 + 255) / 256, 256>>>(xpart, xdbl, xdblq);

        // dt = softplus(xdbl @ dtw_pad^T + b)  (grid 16x32, K=64)
        gemm_f16<<<dim3(D_INNER / 64, ML / 128), 256, MMS_SMEM_BYTES>>>(
            xdblq, 64,
            dtwh + (size_t)l * D_INNER * 64, dtwl + (size_t)l * D_INNER * 64, 64,
            dt_b, dtb, nullptr, D_INNER, 64, 1, 0);

        // chunked selective scan -> y plane (grid 32x8, 256 thr)
        scan_kernel<<<dim3(D_INNER / 32, B_), 256>>>(dtb, xc, xdbl, xz, Al, Dl, yq);

        // out_proj (grid 8x32): mid -> h plane; last -> fp32 for mean
        gemm_f16<<<dim3(D_MODEL / 64, ML / 128), 256, MMS_SMEM_BYTES>>>(
            yq, D_INNER, outwh + outw_off, outwl + outw_off, D_INNER,
            nullptr, last ? ha : nullptr, last ? nullptr : hq,
            D_MODEL, D_INNER, 0, 0);
    }

    mean_cls<<<B_, 512>>>(ha, cls_w1, cls_b1, cls_w2, cls_b2, (float*)d_out);
}

// round 16
// speedup vs baseline: 1.3871x; 1.1499x over previous
#include <cuda_runtime.h>
#include <cuda_fp16.h>
#include <cstdint>

// ---------------- model dims ----------------
#define B_    8
#define L_    512
#define D_IN  128
#define D_MODEL 512
#define N_LAYERS 2
#define D_STATE 16
#define D_CONV  4
#define D_INNER 1024
#define DT_RANK 32
#define ML (B_ * L_)
#define XKS 8                      // split-K / d-slice factor for fused conv+x_proj
#define NCH 8                      // scan chunks over L
#define CHL (L_ / NCH)             // 64 steps per chunk

// ---------------- scratch (fp32) ----------------
__device__ float g_ha[ML * D_MODEL];
__device__ float g_xz[ML * 2 * D_INNER];
__device__ float g_xc[ML * D_INNER];
__device__ float g_xdbl[ML * 64];
__device__ float g_xpart[XKS * ML * 64];
__device__ float g_dt[ML * D_INNER];

// fp16 single planes (activations AND weights)
__device__ __align__(16) __half g_xq[ML * D_IN];
__device__ __align__(16) __half g_piwq[D_MODEL * D_IN];
__device__ __align__(16) __half g_inwq[N_LAYERS * 2 * D_INNER * D_MODEL];
__device__ __align__(16) __half g_outwq[N_LAYERS * D_MODEL * D_INNER];
__device__ __align__(16) __half g_xpwq[N_LAYERS * 64 * D_INNER];
__device__ __align__(16) __half g_dtwq[N_LAYERS * D_INNER * 64];   // padded K 32->64
__device__ __align__(16) __half g_hq[ML * D_MODEL];
__device__ __align__(16) __half g_xdblq[ML * 64];
__device__ __align__(16) __half g_yq[ML * D_INNER];

__device__ __forceinline__ float act_silu(float v) { return v / (1.f + __expf(-v)); }
__device__ __forceinline__ float act_softplus(float v) { return (v > 20.f) ? v : log1pf(__expf(v)); }

// =====================================================================
// PTX helpers
// =====================================================================
__device__ __forceinline__ void ldsm_x4(uint32_t* r, uint32_t addr) {
    asm volatile("ldmatrix.sync.aligned.m8n8.x4.shared.b16 {%0,%1,%2,%3}, [%4];"
                 : "=r"(r[0]), "=r"(r[1]), "=r"(r[2]), "=r"(r[3]) : "r"(addr));
}
__device__ __forceinline__ void mma16816(float* c, const uint32_t* a, const uint32_t* b) {
    asm volatile(
        "mma.sync.aligned.m16n8k16.row.col.f32.f16.f16.f32 "
        "{%0,%1,%2,%3}, {%4,%5,%6,%7}, {%8,%9}, {%0,%1,%2,%3};"
        : "+f"(c[0]), "+f"(c[1]), "+f"(c[2]), "+f"(c[3])
        : "r"(a[0]), "r"(a[1]), "r"(a[2]), "r"(a[3]), "r"(b[0]), "r"(b[1]));
}
__device__ __forceinline__ void cp16(uint32_t dst, const void* src) {
    asm volatile("cp.async.cg.shared.global [%0], [%1], 16;" :: "r"(dst), "l"(src));
}
#define CP_COMMIT() asm volatile("cp.async.commit_group;" ::: "memory")
#define CP_WAIT(n)  asm volatile("cp.async.wait_group %0;" :: "n"(n) : "memory")

__device__ __forceinline__ uint32_t h2_bits(__half2 v) {
    return *reinterpret_cast<const uint32_t*>(&v);
}
__device__ __forceinline__ uint2 quant4(float4 v) {
    __half2 a = __floats2half2_rn(v.x, v.y);
    __half2 b = __floats2half2_rn(v.z, v.w);
    return make_uint2(h2_bits(a), h2_bits(b));
}

// ---------------- all conversions in ONE launch (single planes) ----------------
__global__ void cvt_all(const float* __restrict__ x,    __half* xq,
                        const float* __restrict__ piw,  __half* piwq,
                        const float* __restrict__ inw,  __half* inwq,
                        const float* __restrict__ outw, __half* outwq,
                        const float* __restrict__ xpw,  __half* xpwq,
                        const float* __restrict__ dtw,  __half* dtwq)
{
    int i = blockIdx.x * blockDim.x + threadIdx.x;
    const int n_x   = ML * D_IN / 4;
    const int n_piw = D_MODEL * D_IN / 4;
    const int n_in  = N_LAYERS * 2 * D_INNER * D_MODEL / 4;
    const int n_out = N_LAYERS * D_MODEL * D_INNER / 4;
    const int n_xp  = N_LAYERS * 64 * D_INNER / 4;
    const int n_dt  = N_LAYERS * D_INNER * 8;
    const float* src; __half* q; int si, di;
    if (i < n_x) { src = x; q = xq; si = i; di = i; }
    else if ((i -= n_x) < n_piw) { src = piw; q = piwq; si = i; di = i; }
    else if ((i -= n_piw) < n_in) { src = inw; q = inwq; si = i; di = i; }
    else if ((i -= n_in) < n_out) { src = outw; q = outwq; si = i; di = i; }
    else if ((i -= n_out) < n_xp) { src = xpw; q = xpwq; si = i; di = i; }
    else if ((i -= n_xp) < n_dt) {
        int row = i >> 3, qd = i & 7;
        src = dtw; q = dtwq;
        si = row * 8 + qd;     // 32 floats per row = 8 quads
        di = row * 16 + qd;    // padded 64 halves per row = 16 quads
    }
    else return;
    reinterpret_cast<uint2*>(q)[di] = quant4(reinterpret_cast<const float4*>(src)[si]);
}

// ---------------- common epilogue store ----------------
__device__ __forceinline__ void epi_store(
    float* C, __half* Cq,
    const float* bias, int act, int ldc,
    int r0, int r1, int col, const float* a)
{
    const float b0 = bias ? __ldg(&bias[col]) : 0.f;
    const float b1 = bias ? __ldg(&bias[col + 1]) : 0.f;
    float2 v0 = make_float2(a[0] + b0, a[1] + b1);
    float2 v1 = make_float2(a[2] + b0, a[3] + b1);
    if (act == 1) {
        v0.x = act_softplus(v0.x); v0.y = act_softplus(v0.y);
        v1.x = act_softplus(v1.x); v1.y = act_softplus(v1.y);
    }
    if (C) {
        *reinterpret_cast<float2*>(&C[(size_t)r0 * ldc + col]) = v0;
        *reinterpret_cast<float2*>(&C[(size_t)r1 * ldc + col]) = v1;
    }
    if (Cq) {
        __half2 p0 = __floats2half2_rn(v0.x, v0.y);
        __half2 p1 = __floats2half2_rn(v1.x, v1.y);
        *reinterpret_cast<uint32_t*>(&Cq[(size_t)r0 * ldc + col]) = h2_bits(p0);
        *reinterpret_cast<uint32_t*>(&Cq[(size_t)r1 * ldc + col]) = h2_bits(p1);
    }
}

// =====================================================================
// gemm_f16: CTA 128x64, 256 thr (8 warps 4x2), warp 32x32, K-chunk 64.
// Pure fp16: A single plane, W single plane, ONE MMA term.
// Buffer: Aq @0 (16K), Wq @16K (8K) = 24KB; double 2x24KB; 2 CTA/SM.
// =====================================================================
#define MMS_SMEM_BYTES 49152

__global__ __launch_bounds__(256, 2) void gemm_f16(
    const __half* __restrict__ Aq, int lda,
    const __half* __restrict__ Wq, int ldw,
    const float* __restrict__ bias, float* __restrict__ C,
    __half* __restrict__ Cq,
    int ldc, int K, int act, size_t zstride)
{
    extern __shared__ char smem[];
    const uint32_t sbase = (uint32_t)__cvta_generic_to_shared(smem);
    const int tid = threadIdx.x;
    const int lane = tid & 31;
    const int wid = tid >> 5;
    const int wm = wid & 3;
    const int wn = wid >> 2;
    const int bm = blockIdx.y * 128;
    const int bn = blockIdx.x * 64;
    {
        const int z = blockIdx.z;
        Aq += (size_t)z * K;
        Wq += (size_t)z * K;
        C  += (size_t)z * zstride;
    }

    const int rf = tid >> 3;
    const int sf = tid & 7;
    const uint32_t swb = (uint32_t)(rf * 128 + sf * 16) ^ (((uint32_t)rf & 7u) << 4);

    auto fill = [&](int buf, int k0) {
        const uint32_t bb = sbase + (uint32_t)buf * 24576;
        #pragma unroll
        for (int u = 0; u < 4; u++) {                 // A: 128 rows
            const int row = rf + u * 32;
            const uint32_t sw = swb + (uint32_t)(u * 4096);
            cp16(bb + sw, Aq + (size_t)(bm + row) * lda + k0 + sf * 8);
        }
        #pragma unroll
        for (int u = 0; u < 2; u++) {                 // W: 64 rows
            const int row = rf + u * 32;
            const uint32_t sw = swb + (uint32_t)(u * 4096);
            cp16(bb + 16384 + sw, Wq + (size_t)(bn + row) * ldw + k0 + sf * 8);
        }
    };

    const int l7 = lane & 7;
    const uint32_t xorv = (uint32_t)l7 << 4;
    const int a_row = wm * 32 + l7 + ((lane >> 3) & 1) * 8;
    const uint32_t a_kb = (uint32_t)((lane >> 4) & 1) * 16;
    const int b_row = wn * 32 + ((lane >> 4) & 1) * 8 + l7;
    const uint32_t b_kb = (uint32_t)((lane >> 3) & 1) * 16;

    float acc[2][4][4];
    #pragma unroll
    for (int i = 0; i < 2; i++)
        #pragma unroll
        for (int j = 0; j < 4; j++)
            #pragma unroll
            for (int r = 0; r < 4; r++) acc[i][j][r] = 0.f;

    const int nt = K / 64;

    fill(0, 0);
    CP_COMMIT();

    for (int t = 0; t < nt; t++) {
        const int buf = t & 1;
        if (t + 1 < nt) {
            fill(buf ^ 1, (t + 1) * 64);
            CP_COMMIT();
            CP_WAIT(1);
        } else {
            CP_WAIT(0);
        }
        __syncthreads();

        const uint32_t bb = sbase + (uint32_t)buf * 24576;
        #pragma unroll
        for (int kk = 0; kk < 4; kk++) {
            const uint32_t koff_a = ((uint32_t)(kk * 32) + a_kb) ^ xorv;
            const uint32_t koff_b = ((uint32_t)(kk * 32) + b_kb) ^ xorv;
            uint32_t ah[2][4], bh[2][4];
            #pragma unroll
            for (int i = 0; i < 2; i++)
                ldsm_x4(ah[i], bb + (uint32_t)((a_row + i * 16) * 128) + koff_a);
            #pragma unroll
            for (int jj = 0; jj < 2; jj++)
                ldsm_x4(bh[jj], bb + 16384 + (uint32_t)((b_row + jj * 16) * 128) + koff_b);
            #pragma unroll
            for (int i = 0; i < 2; i++)
                #pragma unroll
                for (int j = 0; j < 4; j++)
                    mma16816(acc[i][j], ah[i], &bh[j >> 1][(j & 1) * 2]);
        }
        __syncthreads();
    }

    const int g = lane >> 2;
    const int t4 = lane & 3;
    #pragma unroll
    for (int i = 0; i < 2; i++) {
        const int r0 = bm + wm * 32 + i * 16 + g;
        const int r1 = r0 + 8;
        #pragma unroll
        for (int j = 0; j < 4; j++) {
            const int col = bn + wn * 32 + j * 8 + t4 * 2;
            epi_store(C, Cq, bias, act, ldc, r0, r1, col, acc[i][j]);
        }
    }
}

// =====================================================================
// FUSED conv + x_proj GEMM (pure fp16 variant).
// =====================================================================
__global__ __launch_bounds__(256, 2) void conv_xproj_mma(
    const float* __restrict__ xz,
    const float* __restrict__ cw,
    const float* __restrict__ cb,
    float* __restrict__ xc,
    const __half* __restrict__ Wq,
    float* __restrict__ C)
{
    extern __shared__ char smem[];
    const uint32_t sbase = (uint32_t)__cvta_generic_to_shared(smem);
    const int tid = threadIdx.x;
    const int lane = tid & 31;
    const int wid = tid >> 5;
    const int wm = wid & 3;
    const int wn = wid >> 2;
    const int bm = blockIdx.y * 128;
    const int z = blockIdx.z;
    const int kbase = z * 128;
    C += (size_t)z * ML * 64;

    const int rf = tid >> 3;
    const int sf = tid & 7;
    const uint32_t swb = (uint32_t)(rf * 128 + sf * 16) ^ (((uint32_t)rf & 7u) << 4);

    auto fillW = [&](int buf, int t) {
        const uint32_t bb = sbase + (uint32_t)buf * 24576;
        const int k0 = kbase + t * 64;
        #pragma unroll
        for (int u = 0; u < 2; u++) {
            const int row = rf + u * 32;
            const uint32_t sw = swb + (uint32_t)(u * 4096);
            cp16(bb + 16384 + sw, Wq + (size_t)row * D_INNER + k0 + sf * 8);
        }
    };

    const int d4g = (tid & 15) * 4;
    const int rowg = tid >> 4;

    auto fillA = [&](int buf, int t) {
        char* bbp = smem + (size_t)buf * 24576;
        const int dcol = kbase + t * 64 + d4g;
        float4 w4[4];
        #pragma unroll
        for (int j = 0; j < 4; j++)
            w4[j] = __ldg(reinterpret_cast<const float4*>(cw + (dcol + j) * 4));
        const float4 b4 = __ldg(reinterpret_cast<const float4*>(cb + dcol));
        const float bbv[4] = {b4.x, b4.y, b4.z, b4.w};

        #pragma unroll
        for (int p = 0; p < 2; p++) {
            const int lrow = rowg * 8 + p * 4;
            const int grow = bm + lrow;
            const int lpos = grow & (L_ - 1);
            const float* base = xz + (size_t)grow * (2 * D_INNER) + dcol;
            float4 v[7];
            #pragma unroll
            for (int k = 0; k < 3; k++)
                v[k] = (lpos - 3 + k >= 0)
                     ? *reinterpret_cast<const float4*>(base + (ptrdiff_t)(k - 3) * 2 * D_INNER)
                     : make_float4(0.f, 0.f, 0.f, 0.f);
            #pragma unroll
            for (int k = 3; k < 7; k++)
                v[k] = *reinterpret_cast<const float4*>(base + (ptrdiff_t)(k - 3) * 2 * D_INNER);

            #pragma unroll
            for (int i = 0; i < 4; i++) {
                const float* e0 = &v[i + 0].x;
                const float* e1 = &v[i + 1].x;
                const float* e2 = &v[i + 2].x;
                const float* e3 = &v[i + 3].x;
                float4 r;
                float* rr = &r.x;
                #pragma unroll
                for (int j = 0; j < 4; j++) {
                    float acc = bbv[j];
                    acc = fmaf(w4[j].x, e0[j], acc);
                    acc = fmaf(w4[j].y, e1[j], acc);
                    acc = fmaf(w4[j].z, e2[j], acc);
                    acc = fmaf(w4[j].w, e3[j], acc);
                    rr[j] = act_silu(acc);
                }
                *reinterpret_cast<float4*>(&xc[(size_t)(grow + i) * D_INNER + dcol]) = r;
                uint32_t off = (uint32_t)((lrow + i) * 128 + d4g * 2);
                uint32_t sw = off ^ ((off >> 3) & 0x70);
                *reinterpret_cast<uint2*>(bbp + sw) = quant4(r);
            }
        }
    };

    const int l7 = lane & 7;
    const uint32_t xorv = (uint32_t)l7 << 4;
    const int a_row = wm * 32 + l7 + ((lane >> 3) & 1) * 8;
    const uint32_t a_kb = (uint32_t)((lane >> 4) & 1) * 16;
    const int b_row = wn * 32 + ((lane >> 4) & 1) * 8 + l7;
    const uint32_t b_kb = (uint32_t)((lane >> 3) & 1) * 16;

    float acc[2][4][4];
    #pragma unroll
    for (int i = 0; i < 2; i++)
        #pragma unroll
        for (int j = 0; j < 4; j++)
            #pragma unroll
            for (int r = 0; r < 4; r++) acc[i][j][r] = 0.f;

    fillW(0, 0);
    CP_COMMIT();
    fillA(0, 0);

    #pragma unroll
    for (int t = 0; t < 2; t++) {
        if (t == 0) {
            fillW(1, 1);
            CP_COMMIT();
            CP_WAIT(1);
        } else {
            CP_WAIT(0);
        }
        __syncthreads();

        const uint32_t bb = sbase + (uint32_t)t * 24576;
        #pragma unroll
        for (int kk = 0; kk < 4; kk++) {
            const uint32_t koff_a = ((uint32_t)(kk * 32) + a_kb) ^ xorv;
            const uint32_t koff_b = ((uint32_t)(kk * 32) + b_kb) ^ xorv;
            uint32_t ah[2][4], bh[2][4];
            #pragma unroll
            for (int i = 0; i < 2; i++)
                ldsm_x4(ah[i], bb + (uint32_t)((a_row + i * 16) * 128) + koff_a);
            #pragma unroll
            for (int jj = 0; jj < 2; jj++)
                ldsm_x4(bh[jj], bb + 16384 + (uint32_t)((b_row + jj * 16) * 128) + koff_b);
            #pragma unroll
            for (int i = 0; i < 2; i++)
                #pragma unroll
                for (int j = 0; j < 4; j++)
                    mma16816(acc[i][j], ah[i], &bh[j >> 1][(j & 1) * 2]);
        }
        __syncthreads();
        if (t == 0) fillA(1, 1);
    }

    const int g = lane >> 2;
    const int t4 = lane & 3;
    #pragma unroll
    for (int i = 0; i < 2; i++) {
        const int r0 = bm + wm * 32 + i * 16 + g;
        const int r1 = r0 + 8;
        #pragma unroll
        for (int j = 0; j < 4; j++) {
            const int col = wn * 32 + j * 8 + t4 * 2;
            epi_store(C, nullptr, nullptr, 0, 64, r0, r1, col, acc[i][j]);
        }
    }
}

// reduce x_proj split-K partials -> xdbl fp32 + fp16 plane
__global__ void reduce_x(const float* __restrict__ part, float* __restrict__ out,
                         __half* __restrict__ oq)
{
    int i = blockIdx.x * blockDim.x + threadIdx.x;
    if (i >= ML * 16) return;
    float4 a = reinterpret_cast<const float4*>(part)[i];
    #pragma unroll
    for (int z = 1; z < XKS; z++) {
        float4 b = reinterpret_cast<const float4*>(part + (size_t)z * ML * 64)[i];
        a.x += b.x; a.y += b.y; a.z += b.z; a.w += b.w;
    }
    reinterpret_cast<float4*>(out)[i] = a;
    reinterpret_cast<uint2*>(oq)[i] = quant4(a);
}

// =====================================================================
// Chunked selective scan (unchanged from r15 winner)
// =====================================================================
__global__ __launch_bounds__(256) void scan_kernel(
    const float* __restrict__ dt, const float* __restrict__ xc,
    const float* __restrict__ xdbl, const float* __restrict__ xz,
    const float* __restrict__ A_log, const float* __restrict__ Dm,
    __half* __restrict__ yq)
{
    const int tid = threadIdx.x;
    const int dl = tid & 31;
    const int c = tid >> 5;
    const int d = blockIdx.x * 32 + dl;
    const int b = blockIdx.y;

    __shared__ float s_h[NCH][32][D_STATE];
    __shared__ float s_sd[NCH][32];
    __shared__ float s_hin[NCH][32][D_STATE];

    float Av[D_STATE];
    #pragma unroll
    for (int s = 0; s < D_STATE; s++) Av[s] = -__expf(__ldg(&A_log[d * D_STATE + s]));
    const float Av0 = Av[0];
    int fastl = 1;
    #pragma unroll
    for (int s = 1; s < D_STATE; s++) {
        float tgt = (s + 1) * Av0;
        fastl &= (fabsf(Av[s] - tgt) <= 1e-4f * fabsf(tgt)) ? 1 : 0;
    }
    const int fast = __syncthreads_and(fastl);

    const size_t rowb = (size_t)b * L_ + c * CHL;

    // Phase A: partial scan from zero
    float h[D_STATE];
    #pragma unroll
    for (int s = 0; s < D_STATE; s++) h[s] = 0.f;
    float sumdt = 0.f;

    for (int i = 0; i < CHL; i++) {
        const size_t row = rowb + i;
        const float dtv = __ldg(&dt[row * D_INNER + d]);
        const float xv  = __ldg(&xc[row * D_INNER + d]);
        sumdt += dtv;
        const float p = dtv * xv;
        const float4* bp = reinterpret_cast<const float4*>(xdbl + row * 64 + 32);
        float4 b0 = __ldg(bp + 0), b1 = __ldg(bp + 1), b2 = __ldg(bp + 2), b3 = __ldg(bp + 3);
        const float Bv[16] = {b0.x, b0.y, b0.z, b0.w, b1.x, b1.y, b1.z, b1.w,
                              b2.x, b2.y, b2.z, b2.w, b3.x, b3.y, b3.z, b3.w};
        if (fast) {
            const float q1 = __expf(dtv * Av0);
            const float q2 = q1 * q1, q3 = q2 * q1, q4 = q2 * q2;
            const float q5 = q4 * q1, q6 = q4 * q2, q7 = q4 * q3, q8 = q4 * q4;
            const float dA[16] = {q1, q2, q3, q4, q5, q6, q7, q8,
                                  q8*q1, q8*q2, q8*q3, q8*q4, q8*q5, q8*q6, q8*q7, q8*q8};
            #pragma unroll
            for (int s = 0; s < D_STATE; s++)
                h[s] = fmaf(dA[s], h[s], p * Bv[s]);
        } else {
            #pragma unroll
            for (int s = 0; s < D_STATE; s++)
                h[s] = fmaf(__expf(dtv * Av[s]), h[s], p * Bv[s]);
        }
    }
    #pragma unroll
    for (int s = 0; s < D_STATE; s++) s_h[c][dl][s] = h[s];
    s_sd[c][dl] = sumdt;
    __syncthreads();

    // Phase B: serial prefix over chunks
    #pragma unroll
    for (int it = 0; it < 2; it++) {
        const int item = tid * 2 + it;
        const int pdl = item >> 4;
        const int ps = item & 15;
        const float av = -__expf(__ldg(&A_log[(blockIdx.x * 32 + pdl) * D_STATE + ps]));
        float hin = 0.f;
        s_hin[0][pdl][ps] = 0.f;
        for (int cc = 1; cc < NCH; cc++) {
            const float P = __expf(av * s_sd[cc - 1][pdl]);
            hin = fmaf(P, hin, s_h[cc - 1][pdl][ps]);
            s_hin[cc][pdl][ps] = hin;
        }
    }
    __syncthreads();

    // Phase C: re-run with incoming state, emit y
    #pragma unroll
    for (int s = 0; s < D_STATE; s++) h[s] = s_hin[c][dl][s];
    const float Dd = __ldg(&Dm[d]);

    for (int i = 0; i < CHL; i++) {
        const size_t row = rowb + i;
        const float dtv = __ldg(&dt[row * D_INNER + d]);
        const float xv  = __ldg(&xc[row * D_INNER + d]);
        const float zv  = __ldg(&xz[row * 2 * D_INNER + D_INNER + d]);
        const float p = dtv * xv;
        const float4* bp = reinterpret_cast<const float4*>(xdbl + row * 64 + 32);
        float4 b0 = __ldg(bp + 0), b1 = __ldg(bp + 1), b2 = __ldg(bp + 2), b3 = __ldg(bp + 3);
        float4 c0 = __ldg(bp + 4), c1 = __ldg(bp + 5), c2 = __ldg(bp + 6), c3 = __ldg(bp + 7);
        const float Bv[16] = {b0.x, b0.y, b0.z, b0.w, b1.x, b1.y, b1.z, b1.w,
                              b2.x, b2.y, b2.z, b2.w, b3.x, b3.y, b3.z, b3.w};
        const float Cv[16] = {c0.x, c0.y, c0.z, c0.w, c1.x, c1.y, c1.z, c1.w,
                              c2.x, c2.y, c2.z, c2.w, c3.x, c3.y, c3.z, c3.w};
        float acc0 = 0.f, acc1 = 0.f;
        if (fast) {
            const float q1 = __expf(dtv * Av0);
            const float q2 = q1 * q1, q3 = q2 * q1, q4 = q2 * q2;
            const float q5 = q4 * q1, q6 = q4 * q2, q7 = q4 * q3, q8 = q4 * q4;
            const float dA[16] = {q1, q2, q3, q4, q5, q6, q7, q8,
                                  q8*q1, q8*q2, q8*q3, q8*q4, q8*q5, q8*q6, q8*q7, q8*q8};
            #pragma unroll
            for (int s = 0; s < D_STATE; s++) {
                float hs = fmaf(dA[s], h[s], p * Bv[s]);
                h[s] = hs;
                if (s & 1) acc1 = fmaf(hs, Cv[s], acc1);
                else       acc0 = fmaf(hs, Cv[s], acc0);
            }
        } else {
            #pragma unroll
            for (int s = 0; s < D_STATE; s++) {
                float hs = fmaf(__expf(dtv * Av[s]), h[s], p * Bv[s]);
                h[s] = hs;
                if (s & 1) acc1 = fmaf(hs, Cv[s], acc1);
                else       acc0 = fmaf(hs, Cv[s], acc0);
            }
        }
        float yv = fmaf(xv, Dd, acc0 + acc1) * act_silu(zv);
        yq[row * D_INNER + d] = __float2half_rn(yv);
    }
}

// ---------------- fused mean + classifier head ----------------
__global__ __launch_bounds__(512) void mean_cls(
    const float* __restrict__ h,
    const float* __restrict__ w1, const float* __restrict__ b1,
    const float* __restrict__ w2, const float* __restrict__ b2,
    float* __restrict__ out)
{
    const int b = blockIdx.x;
    const int t = threadIdx.x;
    __shared__ float hm[D_MODEL];
    __shared__ float hid[64];

    float acc = 0.f;
    const float* p = h + (size_t)b * L_ * D_MODEL + t;
    #pragma unroll 8
    for (int l = 0; l < L_; l++) acc += p[(size_t)l * D_MODEL];
    hm[t] = acc * (1.f / L_);
    __syncthreads();

    if (t < 64) {
        float a = __ldg(&b1[t]);
        const float* wv = w1 + t * D_MODEL;
        for (int k = 0; k < D_MODEL; k += 4) {
            float4 ww = *reinterpret_cast<const float4*>(&wv[k]);
            a = fmaf(hm[k + 0], ww.x, a);
            a = fmaf(hm[k + 1], ww.y, a);
            a = fmaf(hm[k + 2], ww.z, a);
            a = fmaf(hm[k + 3], ww.w, a);
        }
        hid[t] = fmaxf(a, 0.f) * __ldg(&w2[t]);
    }
    __syncthreads();
    if (t == 0) {
        float s = __ldg(&b2[0]);
        #pragma unroll
        for (int u = 0; u < 64; u++) s += hid[u];
        out[b] = s;
    }
}

// ---------------- launch ----------------
extern "C" void kernel_launch(void* const* d_in, const int* in_sizes, int n_in,
                              void* d_out, int out_size)
{
    const float* x          = (const float*)d_in[0];
    const float* proj_in_w  = (const float*)d_in[1];
    const float* proj_in_b  = (const float*)d_in[2];
    const float* in_proj_w  = (const float*)d_in[3];
    const float* conv_w     = (const float*)d_in[4];
    const float* conv_b     = (const float*)d_in[5];
    const float* x_proj_w   = (const float*)d_in[6];
    const float* dt_proj_w  = (const float*)d_in[7];
    const float* dt_proj_b  = (const float*)d_in[8];
    const float* A_log      = (const float*)d_in[9];
    const float* Dm         = (const float*)d_in[10];
    const float* out_proj_w = (const float*)d_in[11];
    const float* cls_w1     = (const float*)d_in[12];
    const float* cls_b1     = (const float*)d_in[13];
    const float* cls_w2     = (const float*)d_in[14];
    const float* cls_b2     = (const float*)d_in[15];

    void* p;
    cudaGetSymbolAddress(&p, g_ha);    float* ha    = (float*)p;
    cudaGetSymbolAddress(&p, g_xz);    float* xz    = (float*)p;
    cudaGetSymbolAddress(&p, g_xc);    float* xc    = (float*)p;
    cudaGetSymbolAddress(&p, g_xdbl);  float* xdbl  = (float*)p;
    cudaGetSymbolAddress(&p, g_xpart); float* xpart = (float*)p;
    cudaGetSymbolAddress(&p, g_dt);    float* dtb   = (float*)p;

    __half *xq, *piwq, *inwq, *outwq, *xpwq, *dtwq, *hq, *xdblq, *yq;
    cudaGetSymbolAddress(&p, g_xq);    xq    = (__half*)p;
    cudaGetSymbolAddress(&p, g_piwq);  piwq  = (__half*)p;
    cudaGetSymbolAddress(&p, g_inwq);  inwq  = (__half*)p;
    cudaGetSymbolAddress(&p, g_outwq); outwq = (__half*)p;
    cudaGetSymbolAddress(&p, g_xpwq);  xpwq  = (__half*)p;
    cudaGetSymbolAddress(&p, g_dtwq);  dtwq  = (__half*)p;
    cudaGetSymbolAddress(&p, g_hq);    hq    = (__half*)p;
    cudaGetSymbolAddress(&p, g_xdblq); xdblq = (__half*)p;
    cudaGetSymbolAddress(&p, g_yq);    yq    = (__half*)p;

    cudaFuncSetAttribute(gemm_f16, cudaFuncAttributeMaxDynamicSharedMemorySize, MMS_SMEM_BYTES);
    cudaFuncSetAttribute(conv_xproj_mma, cudaFuncAttributeMaxDynamicSharedMemorySize, MMS_SMEM_BYTES);

    // L1: all conversions in one launch
    {
        int total = ML * D_IN / 4 + D_MODEL * D_IN / 4
                  + N_LAYERS * 2 * D_INNER * D_MODEL / 4 + N_LAYERS * D_MODEL * D_INNER / 4
                  + N_LAYERS * 64 * D_INNER / 4 + N_LAYERS * D_INNER * 8;
        cvt_all<<<(total + 255) / 256, 256>>>(x, xq, proj_in_w, piwq,
                                              in_proj_w, inwq, out_proj_w, outwq,
                                              x_proj_w, xpwq, dt_proj_w, dtwq);
    }
    // L2: proj_in -> h plane (grid 8x32)
    gemm_f16<<<dim3(D_MODEL / 64, ML / 128), 256, MMS_SMEM_BYTES>>>(
        xq, D_IN, piwq, D_IN, proj_in_b,
        nullptr, hq, D_MODEL, D_IN, 0, 0);

    for (int l = 0; l < N_LAYERS; l++) {
        const size_t inw_off  = (size_t)l * 2 * D_INNER * D_MODEL;
        const size_t outw_off = (size_t)l * D_MODEL * D_INNER;
        const float* cw    = conv_w     + (size_t)l * D_INNER * D_CONV;
        const float* cb    = conv_b     + (size_t)l * D_INNER;
        const float* dt_b  = dt_proj_b  + (size_t)l * D_INNER;
        const float* Al    = A_log      + (size_t)l * D_INNER * D_STATE;
        const float* Dl    = Dm         + (size_t)l * D_INNER;
        const bool last = (l == N_LAYERS - 1);

        // xz = h @ in_w^T  (grid 32x32 = 1024 CTAs)
        gemm_f16<<<dim3(2 * D_INNER / 64, ML / 128), 256, MMS_SMEM_BYTES>>>(
            hq, D_MODEL, inwq + inw_off, D_MODEL,
            nullptr, xz, nullptr, 2 * D_INNER, D_MODEL, 0, 0);

        // fused conv + x_proj split-K (grid 1x32x8)
        conv_xproj_mma<<<dim3(1, ML / 128, XKS), 256, MMS_SMEM_BYTES>>>(
            xz, cw, cb, xc, xpwq + (size_t)l * 64 * D_INNER, xpart);
        reduce_x<<<(ML * 16 + 255) / 256, 256>>>(xpart, xdbl, xdblq);

        // dt = softplus(xdbl @ dtw_pad^T + b)  (grid 16x32, K=64)
        gemm_f16<<<dim3(D_INNER / 64, ML / 128), 256, MMS_SMEM_BYTES>>>(
            xdblq, 64, dtwq + (size_t)l * D_INNER * 64, 64,
            dt_b, dtb, nullptr, D_INNER, 64, 1, 0);

        // chunked selective scan -> y plane (grid 32x8, 256 thr)
        scan_kernel<<<dim3(D_INNER / 32, B_), 256>>>(dtb, xc, xdbl, xz, Al, Dl, yq);

        // out_proj (grid 8x32): mid -> h plane; last -> fp32 for mean
        gemm_f16<<<dim3(D_MODEL / 64, ML / 128), 256, MMS_SMEM_BYTES>>>(
            yq, D_INNER, outwq + outw_off, D_INNER,
            nullptr, last ? ha : nullptr, last ? nullptr : hq,
            D_MODEL, D_INNER, 0, 0);
    }

    mean_cls<<<B_, 512>>>(ha, cls_w1, cls_b1, cls_w2, cls_b2, (float*)d_out);
}

// round 17
// speedup vs baseline: 1.5045x; 1.0846x over previous
#include <cuda_runtime.h>
#include <cuda_fp16.h>
#include <cstdint>

// ---------------- model dims ----------------
#define B_    8
#define L_    512
#define D_IN  128
#define D_MODEL 512
#define N_LAYERS 2
#define D_STATE 16
#define D_CONV  4
#define D_INNER 1024
#define DT_RANK 32
#define ML (B_ * L_)
#define XKS 8
#define NCH 8
#define CHL (L_ / NCH)

// ---------------- scratch ----------------
__device__ float g_ha[ML * D_MODEL];               // final h (fp32, mean)
__device__ float g_xpart[XKS * ML * 64];           // split-K partials (fp32)

// fp16 single planes everywhere
__device__ __align__(16) __half g_xq[ML * D_IN];
__device__ __align__(16) __half g_piwq[D_MODEL * D_IN];
__device__ __align__(16) __half g_inwq[N_LAYERS * 2 * D_INNER * D_MODEL];
__device__ __align__(16) __half g_outwq[N_LAYERS * D_MODEL * D_INNER];
__device__ __align__(16) __half g_xpwq[N_LAYERS * 64 * D_INNER];
__device__ __align__(16) __half g_dtwq[N_LAYERS * D_INNER * 64];   // padded K 32->64
__device__ __align__(16) __half g_hq[ML * D_MODEL];
__device__ __align__(16) __half g_xzq[ML * 2 * D_INNER];
__device__ __align__(16) __half g_xcq[ML * D_INNER];
__device__ __align__(16) __half g_xdblq[ML * 64];
__device__ __align__(16) __half g_dtq[ML * D_INNER];
__device__ __align__(16) __half g_yq[ML * D_INNER];

__device__ __forceinline__ float act_silu(float v) { return v / (1.f + __expf(-v)); }
__device__ __forceinline__ float act_softplus(float v) { return (v > 20.f) ? v : log1pf(__expf(v)); }

// =====================================================================
// PTX helpers
// =====================================================================
__device__ __forceinline__ void ldsm_x4(uint32_t* r, uint32_t addr) {
    asm volatile("ldmatrix.sync.aligned.m8n8.x4.shared.b16 {%0,%1,%2,%3}, [%4];"
                 : "=r"(r[0]), "=r"(r[1]), "=r"(r[2]), "=r"(r[3]) : "r"(addr));
}
__device__ __forceinline__ void mma16816(float* c, const uint32_t* a, const uint32_t* b) {
    asm volatile(
        "mma.sync.aligned.m16n8k16.row.col.f32.f16.f16.f32 "
        "{%0,%1,%2,%3}, {%4,%5,%6,%7}, {%8,%9}, {%0,%1,%2,%3};"
        : "+f"(c[0]), "+f"(c[1]), "+f"(c[2]), "+f"(c[3])
        : "r"(a[0]), "r"(a[1]), "r"(a[2]), "r"(a[3]), "r"(b[0]), "r"(b[1]));
}
__device__ __forceinline__ void cp16(uint32_t dst, const void* src) {
    asm volatile("cp.async.cg.shared.global [%0], [%1], 16;" :: "r"(dst), "l"(src));
}
#define CP_COMMIT() asm volatile("cp.async.commit_group;" ::: "memory")
#define CP_WAIT(n)  asm volatile("cp.async.wait_group %0;" :: "n"(n) : "memory")

__device__ __forceinline__ uint32_t h2_bits(__half2 v) {
    return *reinterpret_cast<const uint32_t*>(&v);
}
__device__ __forceinline__ uint2 quant4(float4 v) {
    __half2 a = __floats2half2_rn(v.x, v.y);
    __half2 b = __floats2half2_rn(v.z, v.w);
    return make_uint2(h2_bits(a), h2_bits(b));
}
__device__ __forceinline__ float4 h4_to_f4(uint2 u) {
    __half2 a = *reinterpret_cast<const __half2*>(&u.x);
    __half2 b = *reinterpret_cast<const __half2*>(&u.y);
    float2 fa = __half22float2(a);
    float2 fb = __half22float2(b);
    return make_float4(fa.x, fa.y, fb.x, fb.y);
}
// unpack 16 halves (uint4) into float[16]
__device__ __forceinline__ void h16_to_f16(uint4 u, float* o) {
    const __half2* p = reinterpret_cast<const __half2*>(&u);
    #pragma unroll
    for (int s = 0; s < 8; s++) {
        float2 f = __half22float2(p[s]);
        o[2 * s] = f.x;
        o[2 * s + 1] = f.y;
    }
}

// ---------------- all conversions in ONE launch ----------------
__global__ void cvt_all(const float* __restrict__ x,    __half* xq,
                        const float* __restrict__ piw,  __half* piwq,
                        const float* __restrict__ inw,  __half* inwq,
                        const float* __restrict__ outw, __half* outwq,
                        const float* __restrict__ xpw,  __half* xpwq,
                        const float* __restrict__ dtw,  __half* dtwq)
{
    int i = blockIdx.x * blockDim.x + threadIdx.x;
    const int n_x   = ML * D_IN / 4;
    const int n_piw = D_MODEL * D_IN / 4;
    const int n_in  = N_LAYERS * 2 * D_INNER * D_MODEL / 4;
    const int n_out = N_LAYERS * D_MODEL * D_INNER / 4;
    const int n_xp  = N_LAYERS * 64 * D_INNER / 4;
    const int n_dt  = N_LAYERS * D_INNER * 8;
    const float* src; __half* q; int si, di;
    if (i < n_x) { src = x; q = xq; si = i; di = i; }
    else if ((i -= n_x) < n_piw) { src = piw; q = piwq; si = i; di = i; }
    else if ((i -= n_piw) < n_in) { src = inw; q = inwq; si = i; di = i; }
    else if ((i -= n_in) < n_out) { src = outw; q = outwq; si = i; di = i; }
    else if ((i -= n_out) < n_xp) { src = xpw; q = xpwq; si = i; di = i; }
    else if ((i -= n_xp) < n_dt) {
        int row = i >> 3, qd = i & 7;
        src = dtw; q = dtwq;
        si = row * 8 + qd;
        di = row * 16 + qd;
    }
    else return;
    reinterpret_cast<uint2*>(q)[di] = quant4(reinterpret_cast<const float4*>(src)[si]);
}

// ---------------- common epilogue store ----------------
__device__ __forceinline__ void epi_store(
    float* C, __half* Cq,
    const float* bias, int act, int ldc,
    int r0, int r1, int col, const float* a)
{
    const float b0 = bias ? __ldg(&bias[col]) : 0.f;
    const float b1 = bias ? __ldg(&bias[col + 1]) : 0.f;
    float2 v0 = make_float2(a[0] + b0, a[1] + b1);
    float2 v1 = make_float2(a[2] + b0, a[3] + b1);
    if (act == 1) {
        v0.x = act_softplus(v0.x); v0.y = act_softplus(v0.y);
        v1.x = act_softplus(v1.x); v1.y = act_softplus(v1.y);
    }
    if (C) {
        *reinterpret_cast<float2*>(&C[(size_t)r0 * ldc + col]) = v0;
        *reinterpret_cast<float2*>(&C[(size_t)r1 * ldc + col]) = v1;
    }
    if (Cq) {
        __half2 p0 = __floats2half2_rn(v0.x, v0.y);
        __half2 p1 = __floats2half2_rn(v1.x, v1.y);
        *reinterpret_cast<uint32_t*>(&Cq[(size_t)r0 * ldc + col]) = h2_bits(p0);
        *reinterpret_cast<uint32_t*>(&Cq[(size_t)r1 * ldc + col]) = h2_bits(p1);
    }
}

// =====================================================================
// gemm_f16 (r16 WINNER, unchanged): CTA 128x64, 256 thr, warp 32x32,
// K-chunk 64, single fp16 planes, 1 MMA term, 2x24KB double buffer.
// =====================================================================
#define MMS_SMEM_BYTES 49152

__global__ __launch_bounds__(256, 2) void gemm_f16(
    const __half* __restrict__ Aq, int lda,
    const __half* __restrict__ Wq, int ldw,
    const float* __restrict__ bias, float* __restrict__ C,
    __half* __restrict__ Cq,
    int ldc, int K, int act, size_t zstride)
{
    extern __shared__ char smem[];
    const uint32_t sbase = (uint32_t)__cvta_generic_to_shared(smem);
    const int tid = threadIdx.x;
    const int lane = tid & 31;
    const int wid = tid >> 5;
    const int wm = wid & 3;
    const int wn = wid >> 2;
    const int bm = blockIdx.y * 128;
    const int bn = blockIdx.x * 64;
    {
        const int z = blockIdx.z;
        Aq += (size_t)z * K;
        Wq += (size_t)z * K;
        C  += (size_t)z * zstride;
    }

    const int rf = tid >> 3;
    const int sf = tid & 7;
    const uint32_t swb = (uint32_t)(rf * 128 + sf * 16) ^ (((uint32_t)rf & 7u) << 4);

    auto fill = [&](int buf, int k0) {
        const uint32_t bb = sbase + (uint32_t)buf * 24576;
        #pragma unroll
        for (int u = 0; u < 4; u++) {
            const int row = rf + u * 32;
            const uint32_t sw = swb + (uint32_t)(u * 4096);
            cp16(bb + sw, Aq + (size_t)(bm + row) * lda + k0 + sf * 8);
        }
        #pragma unroll
        for (int u = 0; u < 2; u++) {
            const int row = rf + u * 32;
            const uint32_t sw = swb + (uint32_t)(u * 4096);
            cp16(bb + 16384 + sw, Wq + (size_t)(bn + row) * ldw + k0 + sf * 8);
        }
    };

    const int l7 = lane & 7;
    const uint32_t xorv = (uint32_t)l7 << 4;
    const int a_row = wm * 32 + l7 + ((lane >> 3) & 1) * 8;
    const uint32_t a_kb = (uint32_t)((lane >> 4) & 1) * 16;
    const int b_row = wn * 32 + ((lane >> 4) & 1) * 8 + l7;
    const uint32_t b_kb = (uint32_t)((lane >> 3) & 1) * 16;

    float acc[2][4][4];
    #pragma unroll
    for (int i = 0; i < 2; i++)
        #pragma unroll
        for (int j = 0; j < 4; j++)
            #pragma unroll
            for (int r = 0; r < 4; r++) acc[i][j][r] = 0.f;

    const int nt = K / 64;

    fill(0, 0);
    CP_COMMIT();

    for (int t = 0; t < nt; t++) {
        const int buf = t & 1;
        if (t + 1 < nt) {
            fill(buf ^ 1, (t + 1) * 64);
            CP_COMMIT();
            CP_WAIT(1);
        } else {
            CP_WAIT(0);
        }
        __syncthreads();

        const uint32_t bb = sbase + (uint32_t)buf * 24576;
        #pragma unroll
        for (int kk = 0; kk < 4; kk++) {
            const uint32_t koff_a = ((uint32_t)(kk * 32) + a_kb) ^ xorv;
            const uint32_t koff_b = ((uint32_t)(kk * 32) + b_kb) ^ xorv;
            uint32_t ah[2][4], bh[2][4];
            #pragma unroll
            for (int i = 0; i < 2; i++)
                ldsm_x4(ah[i], bb + (uint32_t)((a_row + i * 16) * 128) + koff_a);
            #pragma unroll
            for (int jj = 0; jj < 2; jj++)
                ldsm_x4(bh[jj], bb + 16384 + (uint32_t)((b_row + jj * 16) * 128) + koff_b);
            #pragma unroll
            for (int i = 0; i < 2; i++)
                #pragma unroll
                for (int j = 0; j < 4; j++)
                    mma16816(acc[i][j], ah[i], &bh[j >> 1][(j & 1) * 2]);
        }
        __syncthreads();
    }

    const int g = lane >> 2;
    const int t4 = lane & 3;
    #pragma unroll
    for (int i = 0; i < 2; i++) {
        const int r0 = bm + wm * 32 + i * 16 + g;
        const int r1 = r0 + 8;
        #pragma unroll
        for (int j = 0; j < 4; j++) {
            const int col = bn + wn * 32 + j * 8 + t4 * 2;
            epi_store(C, Cq, bias, act, ldc, r0, r1, col, acc[i][j]);
        }
    }
}

// =====================================================================
// FUSED conv + x_proj GEMM: xz read as fp16 (uint2 loads), xc emitted fp16.
// =====================================================================
__global__ __launch_bounds__(256, 2) void conv_xproj_mma(
    const __half* __restrict__ xzq,
    const float* __restrict__ cw,
    const float* __restrict__ cb,
    __half* __restrict__ xcq,
    const __half* __restrict__ Wq,
    float* __restrict__ C)
{
    extern __shared__ char smem[];
    const uint32_t sbase = (uint32_t)__cvta_generic_to_shared(smem);
    const int tid = threadIdx.x;
    const int lane = tid & 31;
    const int wid = tid >> 5;
    const int wm = wid & 3;
    const int wn = wid >> 2;
    const int bm = blockIdx.y * 128;
    const int z = blockIdx.z;
    const int kbase = z * 128;
    C += (size_t)z * ML * 64;

    const int rf = tid >> 3;
    const int sf = tid & 7;
    const uint32_t swb = (uint32_t)(rf * 128 + sf * 16) ^ (((uint32_t)rf & 7u) << 4);

    auto fillW = [&](int buf, int t) {
        const uint32_t bb = sbase + (uint32_t)buf * 24576;
        const int k0 = kbase + t * 64;
        #pragma unroll
        for (int u = 0; u < 2; u++) {
            const int row = rf + u * 32;
            const uint32_t sw = swb + (uint32_t)(u * 4096);
            cp16(bb + 16384 + sw, Wq + (size_t)row * D_INNER + k0 + sf * 8);
        }
    };

    const int d4g = (tid & 15) * 4;
    const int rowg = tid >> 4;

    auto fillA = [&](int buf, int t) {
        char* bbp = smem + (size_t)buf * 24576;
        const int dcol = kbase + t * 64 + d4g;
        float4 w4[4];
        #pragma unroll
        for (int j = 0; j < 4; j++)
            w4[j] = __ldg(reinterpret_cast<const float4*>(cw + (dcol + j) * 4));
        const float4 b4 = __ldg(reinterpret_cast<const float4*>(cb + dcol));
        const float bbv[4] = {b4.x, b4.y, b4.z, b4.w};

        #pragma unroll
        for (int p = 0; p < 2; p++) {
            const int lrow = rowg * 8 + p * 4;
            const int grow = bm + lrow;
            const int lpos = grow & (L_ - 1);
            const __half* base = xzq + (size_t)grow * (2 * D_INNER) + dcol;
            float4 v[7];
            #pragma unroll
            for (int k = 0; k < 3; k++)
                v[k] = (lpos - 3 + k >= 0)
                     ? h4_to_f4(__ldg(reinterpret_cast<const uint2*>(base + (ptrdiff_t)(k - 3) * 2 * D_INNER)))
                     : make_float4(0.f, 0.f, 0.f, 0.f);
            #pragma unroll
            for (int k = 3; k < 7; k++)
                v[k] = h4_to_f4(__ldg(reinterpret_cast<const uint2*>(base + (ptrdiff_t)(k - 3) * 2 * D_INNER)));

            #pragma unroll
            for (int i = 0; i < 4; i++) {
                const float* e0 = &v[i + 0].x;
                const float* e1 = &v[i + 1].x;
                const float* e2 = &v[i + 2].x;
                const float* e3 = &v[i + 3].x;
                float4 r;
                float* rr = &r.x;
                #pragma unroll
                for (int j = 0; j < 4; j++) {
                    float acc = bbv[j];
                    acc = fmaf(w4[j].x, e0[j], acc);
                    acc = fmaf(w4[j].y, e1[j], acc);
                    acc = fmaf(w4[j].z, e2[j], acc);
                    acc = fmaf(w4[j].w, e3[j], acc);
                    rr[j] = act_silu(acc);
                }
                uint2 q = quant4(r);
                *reinterpret_cast<uint2*>(&xcq[(size_t)(grow + i) * D_INNER + dcol]) = q;
                uint32_t off = (uint32_t)((lrow + i) * 128 + d4g * 2);
                uint32_t sw = off ^ ((off >> 3) & 0x70);
                *reinterpret_cast<uint2*>(bbp + sw) = q;
            }
        }
    };

    const int l7 = lane & 7;
    const uint32_t xorv = (uint32_t)l7 << 4;
    const int a_row = wm * 32 + l7 + ((lane >> 3) & 1) * 8;
    const uint32_t a_kb = (uint32_t)((lane >> 4) & 1) * 16;
    const int b_row = wn * 32 + ((lane >> 4) & 1) * 8 + l7;
    const uint32_t b_kb = (uint32_t)((lane >> 3) & 1) * 16;

    float acc[2][4][4];
    #pragma unroll
    for (int i = 0; i < 2; i++)
        #pragma unroll
        for (int j = 0; j < 4; j++)
            #pragma unroll
            for (int r = 0; r < 4; r++) acc[i][j][r] = 0.f;

    fillW(0, 0);
    CP_COMMIT();
    fillA(0, 0);

    #pragma unroll
    for (int t = 0; t < 2; t++) {
        if (t == 0) {
            fillW(1, 1);
            CP_COMMIT();
            CP_WAIT(1);
        } else {
            CP_WAIT(0);
        }
        __syncthreads();

        const uint32_t bb = sbase + (uint32_t)t * 24576;
        #pragma unroll
        for (int kk = 0; kk < 4; kk++) {
            const uint32_t koff_a = ((uint32_t)(kk * 32) + a_kb) ^ xorv;
            const uint32_t koff_b = ((uint32_t)(kk * 32) + b_kb) ^ xorv;
            uint32_t ah[2][4], bh[2][4];
            #pragma unroll
            for (int i = 0; i < 2; i++)
                ldsm_x4(ah[i], bb + (uint32_t)((a_row + i * 16) * 128) + koff_a);
            #pragma unroll
            for (int jj = 0; jj < 2; jj++)
                ldsm_x4(bh[jj], bb + 16384 + (uint32_t)((b_row + jj * 16) * 128) + koff_b);
            #pragma unroll
            for (int i = 0; i < 2; i++)
                #pragma unroll
                for (int j = 0; j < 4; j++)
                    mma16816(acc[i][j], ah[i], &bh[j >> 1][(j & 1) * 2]);
        }
        __syncthreads();
        if (t == 0) fillA(1, 1);
    }

    const int g = lane >> 2;
    const int t4 = lane & 3;
    #pragma unroll
    for (int i = 0; i < 2; i++) {
        const int r0 = bm + wm * 32 + i * 16 + g;
        const int r1 = r0 + 8;
        #pragma unroll
        for (int j = 0; j < 4; j++) {
            const int col = wn * 32 + j * 8 + t4 * 2;
            epi_store(C, nullptr, nullptr, 0, 64, r0, r1, col, acc[i][j]);
        }
    }
}

// reduce x_proj split-K partials -> fp16 plane only
__global__ void reduce_x(const float* __restrict__ part, __half* __restrict__ oq)
{
    int i = blockIdx.x * blockDim.x + threadIdx.x;
    if (i >= ML * 16) return;
    float4 a = reinterpret_cast<const float4*>(part)[i];
    #pragma unroll
    for (int z = 1; z < XKS; z++) {
        float4 b = reinterpret_cast<const float4*>(part + (size_t)z * ML * 64)[i];
        a.x += b.x; a.y += b.y; a.z += b.z; a.w += b.w;
    }
    reinterpret_cast<uint2*>(oq)[i] = quant4(a);
}

// =====================================================================
// Chunked selective scan — all inputs fp16 (B/C rows: 1 uint4 each).
// =====================================================================
__global__ __launch_bounds__(256) void scan_kernel(
    const __half* __restrict__ dtq, const __half* __restrict__ xcq,
    const __half* __restrict__ xdblq, const __half* __restrict__ xzq,
    const float* __restrict__ A_log, const float* __restrict__ Dm,
    __half* __restrict__ yq)
{
    const int tid = threadIdx.x;
    const int dl = tid & 31;
    const int c = tid >> 5;
    const int d = blockIdx.x * 32 + dl;
    const int b = blockIdx.y;

    __shared__ float s_h[NCH][32][D_STATE];
    __shared__ float s_sd[NCH][32];
    __shared__ float s_hin[NCH][32][D_STATE];

    float Av[D_STATE];
    #pragma unroll
    for (int s = 0; s < D_STATE; s++) Av[s] = -__expf(__ldg(&A_log[d * D_STATE + s]));
    const float Av0 = Av[0];
    int fastl = 1;
    #pragma unroll
    for (int s = 1; s < D_STATE; s++) {
        float tgt = (s + 1) * Av0;
        fastl &= (fabsf(Av[s] - tgt) <= 1e-4f * fabsf(tgt)) ? 1 : 0;
    }
    const int fast = __syncthreads_and(fastl);

    const size_t rowb = (size_t)b * L_ + c * CHL;

    // Phase A: partial scan from zero
    float h[D_STATE];
    #pragma unroll
    for (int s = 0; s < D_STATE; s++) h[s] = 0.f;
    float sumdt = 0.f;

    for (int i = 0; i < CHL; i++) {
        const size_t row = rowb + i;
        const float dtv = __half2float(__ldg(&dtq[row * D_INNER + d]));
        const float xv  = __half2float(__ldg(&xcq[row * D_INNER + d]));
        sumdt += dtv;
        const float p = dtv * xv;
        float Bv[16];
        h16_to_f16(__ldg(reinterpret_cast<const uint4*>(xdblq + row * 64 + 32)), Bv);
        if (fast) {
            const float q1 = __expf(dtv * Av0);
            const float q2 = q1 * q1, q3 = q2 * q1, q4 = q2 * q2;
            const float q5 = q4 * q1, q6 = q4 * q2, q7 = q4 * q3, q8 = q4 * q4;
            const float dA[16] = {q1, q2, q3, q4, q5, q6, q7, q8,
                                  q8*q1, q8*q2, q8*q3, q8*q4, q8*q5, q8*q6, q8*q7, q8*q8};
            #pragma unroll
            for (int s = 0; s < D_STATE; s++)
                h[s] = fmaf(dA[s], h[s], p * Bv[s]);
        } else {
            #pragma unroll
            for (int s = 0; s < D_STATE; s++)
                h[s] = fmaf(__expf(dtv * Av[s]), h[s], p * Bv[s]);
        }
    }
    #pragma unroll
    for (int s = 0; s < D_STATE; s++) s_h[c][dl][s] = h[s];
    s_sd[c][dl] = sumdt;
    __syncthreads();

    // Phase B: serial prefix over chunks
    #pragma unroll
    for (int it = 0; it < 2; it++) {
        const int item = tid * 2 + it;
        const int pdl = item >> 4;
        const int ps = item & 15;
        const float av = -__expf(__ldg(&A_log[(blockIdx.x * 32 + pdl) * D_STATE + ps]));
        float hin = 0.f;
        s_hin[0][pdl][ps] = 0.f;
        for (int cc = 1; cc < NCH; cc++) {
            const float P = __expf(av * s_sd[cc - 1][pdl]);
            hin = fmaf(P, hin, s_h[cc - 1][pdl][ps]);
            s_hin[cc][pdl][ps] = hin;
        }
    }
    __syncthreads();

    // Phase C: re-run with incoming state, emit y
    #pragma unroll
    for (int s = 0; s < D_STATE; s++) h[s] = s_hin[c][dl][s];
    const float Dd = __ldg(&Dm[d]);

    for (int i = 0; i < CHL; i++) {
        const size_t row = rowb + i;
        const float dtv = __half2float(__ldg(&dtq[row * D_INNER + d]));
        const float xv  = __half2float(__ldg(&xcq[row * D_INNER + d]));
        const float zv  = __half2float(__ldg(&xzq[row * 2 * D_INNER + D_INNER + d]));
        const float p = dtv * xv;
        float Bv[16], Cv[16];
        h16_to_f16(__ldg(reinterpret_cast<const uint4*>(xdblq + row * 64 + 32)), Bv);
        h16_to_f16(__ldg(reinterpret_cast<const uint4*>(xdblq + row * 64 + 48)), Cv);
        float acc0 = 0.f, acc1 = 0.f;
        if (fast) {
            const float q1 = __expf(dtv * Av0);
            const float q2 = q1 * q1, q3 = q2 * q1, q4 = q2 * q2;
            const float q5 = q4 * q1, q6 = q4 * q2, q7 = q4 * q3, q8 = q4 * q4;
            const float dA[16] = {q1, q2, q3, q4, q5, q6, q7, q8,
                                  q8*q1, q8*q2, q8*q3, q8*q4, q8*q5, q8*q6, q8*q7, q8*q8};
            #pragma unroll
            for (int s = 0; s < D_STATE; s++) {
                float hs = fmaf(dA[s], h[s], p * Bv[s]);
                h[s] = hs;
                if (s & 1) acc1 = fmaf(hs, Cv[s], acc1);
                else       acc0 = fmaf(hs, Cv[s], acc0);
            }
        } else {
            #pragma unroll
            for (int s = 0; s < D_STATE; s++) {
                float hs = fmaf(__expf(dtv * Av[s]), h[s], p * Bv[s]);
                h[s] = hs;
                if (s & 1) acc1 = fmaf(hs, Cv[s], acc1);
                else       acc0 = fmaf(hs, Cv[s], acc0);
            }
        }
        float yv = fmaf(xv, Dd, acc0 + acc1) * act_silu(zv);
        yq[row * D_INNER + d] = __float2half_rn(yv);
    }
}

// ---------------- fused mean + classifier head ----------------
__global__ __launch_bounds__(512) void mean_cls(
    const float* __restrict__ h,
    const float* __restrict__ w1, const float* __restrict__ b1,
    const float* __restrict__ w2, const float* __restrict__ b2,
    float* __restrict__ out)
{
    const int b = blockIdx.x;
    const int t = threadIdx.x;
    __shared__ float hm[D_MODEL];
    __shared__ float hid[64];

    float acc = 0.f;
    const float* p = h + (size_t)b * L_ * D_MODEL + t;
    #pragma unroll 8
    for (int l = 0; l < L_; l++) acc += p[(size_t)l * D_MODEL];
    hm[t] = acc * (1.f / L_);
    __syncthreads();

    if (t < 64) {
        float a = __ldg(&b1[t]);
        const float* wv = w1 + t * D_MODEL;
        for (int k = 0; k < D_MODEL; k += 4) {
            float4 ww = *reinterpret_cast<const float4*>(&wv[k]);
            a = fmaf(hm[k + 0], ww.x, a);
            a = fmaf(hm[k + 1], ww.y, a);
            a = fmaf(hm[k + 2], ww.z, a);
            a = fmaf(hm[k + 3], ww.w, a);
        }
        hid[t] = fmaxf(a, 0.f) * __ldg(&w2[t]);
    }
    __syncthreads();
    if (t == 0) {
        float s = __ldg(&b2[0]);
        #pragma unroll
        for (int u = 0; u < 64; u++) s += hid[u];
        out[b] = s;
    }
}

// ---------------- launch ----------------
extern "C" void kernel_launch(void* const* d_in, const int* in_sizes, int n_in,
                              void* d_out, int out_size)
{
    const float* x          = (const float*)d_in[0];
    const float* proj_in_w  = (const float*)d_in[1];
    const float* proj_in_b  = (const float*)d_in[2];
    const float* in_proj_w  = (const float*)d_in[3];
    const float* conv_w     = (const float*)d_in[4];
    const float* conv_b     = (const float*)d_in[5];
    const float* x_proj_w   = (const float*)d_in[6];
    const float* dt_proj_w  = (const float*)d_in[7];
    const float* dt_proj_b  = (const float*)d_in[8];
    const float* A_log      = (const float*)d_in[9];
    const float* Dm         = (const float*)d_in[10];
    const float* out_proj_w = (const float*)d_in[11];
    const float* cls_w1     = (const float*)d_in[12];
    const float* cls_b1     = (const float*)d_in[13];
    const float* cls_w2     = (const float*)d_in[14];
    const float* cls_b2     = (const float*)d_in[15];

    void* p;
    cudaGetSymbolAddress(&p, g_ha);    float* ha    = (float*)p;
    cudaGetSymbolAddress(&p, g_xpart); float* xpart = (float*)p;

    __half *xq, *piwq, *inwq, *outwq, *xpwq, *dtwq;
    __half *hq, *xzq, *xcq, *xdblq, *dtq, *yq;
    cudaGetSymbolAddress(&p, g_xq);    xq    = (__half*)p;
    cudaGetSymbolAddress(&p, g_piwq);  piwq  = (__half*)p;
    cudaGetSymbolAddress(&p, g_inwq);  inwq  = (__half*)p;
    cudaGetSymbolAddress(&p, g_outwq); outwq = (__half*)p;
    cudaGetSymbolAddress(&p, g_xpwq);  xpwq  = (__half*)p;
    cudaGetSymbolAddress(&p, g_dtwq);  dtwq  = (__half*)p;
    cudaGetSymbolAddress(&p, g_hq);    hq    = (__half*)p;
    cudaGetSymbolAddress(&p, g_xzq);   xzq   = (__half*)p;
    cudaGetSymbolAddress(&p, g_xcq);   xcq   = (__half*)p;
    cudaGetSymbolAddress(&p, g_xdblq); xdblq = (__half*)p;
    cudaGetSymbolAddress(&p, g_dtq);   dtq   = (__half*)p;
    cudaGetSymbolAddress(&p, g_yq);    yq    = (__half*)p;

    cudaFuncSetAttribute(gemm_f16, cudaFuncAttributeMaxDynamicSharedMemorySize, MMS_SMEM_BYTES);
    cudaFuncSetAttribute(conv_xproj_mma, cudaFuncAttributeMaxDynamicSharedMemorySize, MMS_SMEM_BYTES);

    // L1: all conversions in one launch
    {
        int total = ML * D_IN / 4 + D_MODEL * D_IN / 4
                  + N_LAYERS * 2 * D_INNER * D_MODEL / 4 + N_LAYERS * D_MODEL * D_INNER / 4
                  + N_LAYERS * 64 * D_INNER / 4 + N_LAYERS * D_INNER * 8;
        cvt_all<<<(total + 255) / 256, 256>>>(x, xq, proj_in_w, piwq,
                                              in_proj_w, inwq, out_proj_w, outwq,
                                              x_proj_w, xpwq, dt_proj_w, dtwq);
    }
    // L2: proj_in -> h plane (grid 8x32)
    gemm_f16<<<dim3(D_MODEL / 64, ML / 128), 256, MMS_SMEM_BYTES>>>(
        xq, D_IN, piwq, D_IN, proj_in_b,
        nullptr, hq, D_MODEL, D_IN, 0, 0);

    for (int l = 0; l < N_LAYERS; l++) {
        const size_t inw_off  = (size_t)l * 2 * D_INNER * D_MODEL;
        const size_t outw_off = (size_t)l * D_MODEL * D_INNER;
        const float* cw    = conv_w     + (size_t)l * D_INNER * D_CONV;
        const float* cb    = conv_b     + (size_t)l * D_INNER;
        const float* dt_b  = dt_proj_b  + (size_t)l * D_INNER;
        const float* Al    = A_log      + (size_t)l * D_INNER * D_STATE;
        const float* Dl    = Dm         + (size_t)l * D_INNER;
        const bool last = (l == N_LAYERS - 1);

        // xz = h @ in_w^T -> fp16 plane (grid 32x32)
        gemm_f16<<<dim3(2 * D_INNER / 64, ML / 128), 256, MMS_SMEM_BYTES>>>(
            hq, D_MODEL, inwq + inw_off, D_MODEL,
            nullptr, nullptr, xzq, 2 * D_INNER, D_MODEL, 0, 0);

        // fused conv + x_proj split-K (grid 1x32x8)
        conv_xproj_mma<<<dim3(1, ML / 128, XKS), 256, MMS_SMEM_BYTES>>>(
            xzq, cw, cb, xcq, xpwq + (size_t)l * 64 * D_INNER, xpart);
        reduce_x<<<(ML * 16 + 255) / 256, 256>>>(xpart, xdblq);

        // dt = softplus(xdbl @ dtw_pad^T + b) -> fp16 (grid 16x32, K=64)
        gemm_f16<<<dim3(D_INNER / 64, ML / 128), 256, MMS_SMEM_BYTES>>>(
            xdblq, 64, dtwq + (size_t)l * D_INNER * 64, 64,
            dt_b, nullptr, dtq, D_INNER, 64, 1, 0);

        // chunked selective scan -> y plane (grid 32x8, 256 thr)
        scan_kernel<<<dim3(D_INNER / 32, B_), 256>>>(dtq, xcq, xdblq, xzq, Al, Dl, yq);

        // out_proj (grid 8x32): mid -> h plane; last -> fp32 for mean
        gemm_f16<<<dim3(D_MODEL / 64, ML / 128), 256, MMS_SMEM_BYTES>>>(
            yq, D_INNER, outwq + outw_off, D_INNER,
            nullptr, last ? ha : nullptr, last ? nullptr : hq,
            D_MODEL, D_INNER, 0, 0);
    }

    mean_cls<<<B_, 512>>>(ha, cls_w1, cls_b1, cls_w2, cls_b2, (float*)d_out);
}